// round 12
// baseline (speedup 1.0000x reference)
#include <cuda_runtime.h>
#include <cuda_fp16.h>
#include <math.h>
#include <float.h>
#include <stdint.h>

#define NPTS 80000
#define CH   64
#define KN   27
#define NB   2
#define NXX  3
#define CAQ  192
#define HID  12

// ---------------- scratch (device globals; no allocation allowed) ----------
__device__ float g_conv[NPTS*CH];
__device__ float g_kx0[NPTS*CH];
__device__ float g_kx1[NPTS*CH];
__device__ float g_kx2[NPTS*CH];
__device__ __half2 g_hiA[NPTS*CH/2];
__device__ __half2 g_hiB[NPTS*CH/2];
__device__ uint32_t g_wswz[5*KN*2048];      // W_hi fp16, mma-fragment packed (8KB/tap)
__device__ float g_sum[5*CH], g_sumsq[5*CH];
__device__ float g_segsum[NB*CAQ], g_segmax[NB*CAQ], g_att[NB*CAQ], g_wsig[NXX];

// ---------------- helpers ----------------------------------------------------
__device__ __forceinline__ uint32_t smem_u32(const void* p){
  uint32_t a;
  asm("{ .reg .u64 t; cvta.to.shared.u64 t, %1; cvt.u32.u64 %0, t; }" : "=r"(a) : "l"(p));
  return a;
}
__device__ __forceinline__ void ldsm_x4(uint32_t addr, uint32_t* r){
  asm volatile("ldmatrix.sync.aligned.m8n8.x4.shared.b16 {%0,%1,%2,%3}, [%4];"
    : "=r"(r[0]),"=r"(r[1]),"=r"(r[2]),"=r"(r[3]) : "r"(addr));
}
__device__ __forceinline__ void hmma(float* c, const uint32_t* a, uint32_t b0, uint32_t b1){
  asm volatile(
    "mma.sync.aligned.m16n8k16.row.col.f32.f16.f16.f32 "
    "{%0,%1,%2,%3}, {%4,%5,%6,%7}, {%8,%9}, {%0,%1,%2,%3};"
    : "+f"(c[0]), "+f"(c[1]), "+f"(c[2]), "+f"(c[3])
    : "r"(a[0]), "r"(a[1]), "r"(a[2]), "r"(a[3]), "r"(b0), "r"(b1));
}
__device__ __forceinline__ void cp16z(uint32_t sdst, const void* gsrc, int srcsz){
  asm volatile("cp.async.cg.shared.global [%0], [%1], 16, %2;" :: "r"(sdst), "l"(gsrc), "r"(srcsz));
}
#define CP_COMMIT() asm volatile("cp.async.commit_group;" ::: "memory")
#define CP_WAIT2()  asm volatile("cp.async.wait_group 2;" ::: "memory")

__device__ __forceinline__ void atomicMaxFloat(float* addr, float val){
  int* ai = (int*)addr;
  int old = *ai;
  while (true){
    float fo = __int_as_float(old);
    if (fo >= val) break;
    int assumed = old;
    old = atomicCAS(ai, assumed, __float_as_int(val));
    if (old == assumed) break;
  }
}

// ---------------- weight prep: pack W_hi into mma B-fragment order ----------
// Per tap: u32 slot = ((wn*4+q)*2+quad)*128 + L*4 + r
//   n  = wn*32 + quad*16 + (r>>1)*8 + (L>>2)
//   kk = q*16 + (L&3)*2 + (r&1)*8
__global__ void wprep_kernel(const float* __restrict__ W1,
                             const float* __restrict__ W2,
                             const float* __restrict__ Wk){
  int gid = blockIdx.x*256 + threadIdx.x;
  if (gid >= 5*KN*2048) return;
  int slot = gid & 2047;
  int tk = gid >> 11;
  int l = tk/KN, k = tk - l*KN;
  const float* Ws = (l==0)? W1 : (l==1)? W2 : (Wk + (size_t)(l-2)*KN*CH*CH);
  int r    = slot & 3;
  int L    = (slot >> 2) & 31;
  int rest = slot >> 7;
  int quad = rest & 1;
  int q    = (rest >> 1) & 3;
  int wn   = rest >> 3;
  int n  = wn*32 + quad*16 + (r>>1)*8 + (L>>2);
  int kk = q*16 + (L&3)*2 + (r&1)*8;
  __half b0 = __float2half(Ws[k*CH*CH + kk*CH + n]);
  __half b1 = __float2half(Ws[k*CH*CH + (kk+1)*CH + n]);
  g_wswz[tk*2048 + slot] =
      (uint32_t)__half_as_ushort(b0) | ((uint32_t)__half_as_ushort(b1) << 16);
}

// ---------------- fp32 -> fp16 conversion of layer-0 input ------------------
__global__ void cvt_kernel(const float4* __restrict__ x,
                           __half2* __restrict__ ho){
  int i4 = blockIdx.x*256 + threadIdx.x;
  float4 v = x[i4];
  ho[2*i4]   = __halves2half2(__float2half(v.x), __float2half(v.y));
  ho[2*i4+1] = __halves2half2(__float2half(v.z), __float2half(v.w));
}

// ---------------- one-shot clears (stats x5 layers + segment buffers) -------
__global__ void clear_all_kernel(){
  int t = blockIdx.x*256 + threadIdx.x;
  if (t < 5*CH){ g_sum[t]=0.f; g_sumsq[t]=0.f; }
  if (t < NB*CAQ){ g_segsum[t]=0.f; g_segmax[t]=-FLT_MAX; }
}

// ---------------- HMMA gathered conv -----------------------------------------
// Warp-private tiling: 8 warps x (M=16 rows, N=64). Single-pass fp16.
// A: per-warp 2KB x4 ring (64KB), NO mainloop barriers, wait_group 2.
// B: registers via LDG.128 (fragment-packed gmem, L2-hot), per-q double buffer.
#define NBR_OFF 65536
#define SM_DYN (65536 + 13824 + 1024)

__device__ __forceinline__ void ldgB64(const uint4* __restrict__ bw,
                                       int k, int q, int L, uint32_t* B){
  const uint4* p0 = bw + (size_t)k*512 + (size_t)(q*2)*32 + L;       // n 0..31
  const uint4* p1 = p0 + 8*32;                                       // n 32..63
  uint4 v0 = __ldg(p0);
  uint4 v1 = __ldg(p0 + 32);
  uint4 v2 = __ldg(p1);
  uint4 v3 = __ldg(p1 + 32);
  B[0]=v0.x;  B[1]=v0.y;  B[2]=v0.z;  B[3]=v0.w;
  B[4]=v1.x;  B[5]=v1.y;  B[6]=v1.z;  B[7]=v1.w;
  B[8]=v2.x;  B[9]=v2.y;  B[10]=v2.z; B[11]=v2.w;
  B[12]=v3.x; B[13]=v3.y; B[14]=v3.z; B[15]=v3.w;
}

// warp-private A fill: 16 rows x 128B; lane L -> row L>>1, half L&1 (4x16B)
__device__ __forceinline__ void fillA(
    int k, uint32_t bufbase, int w, int L, const int* __restrict__ snbr,
    const __half* __restrict__ hi)
{
  int rl   = L >> 1;
  int half = L & 1;
  int idx = snbr[(w*16 + rl)*KN + k];
  int sz = idx>=0 ? 16 : 0;
  int sidx = idx>=0 ? idx : 0;
  const char* asrc = (const char*)(hi + (size_t)sidx*CH);
  uint32_t rbase = bufbase + (uint32_t)rl*128;
  int xr = rl & 7;
#pragma unroll
  for (int j=0;j<4;j++){
    int c = half*4 + j;
    int sw = c ^ xr;
    cp16z(rbase + sw*16, asrc + c*16, sz);
  }
}

__global__ void __launch_bounds__(256,2) conv_mma(
    const __half* __restrict__ hi,
    const int* __restrict__ nbr, const uint32_t* __restrict__ bswz,
    float* __restrict__ dst, int layer)
{
  extern __shared__ char smraw[];
  char* sm = (char*)(((uintptr_t)smraw + 1023) & ~(uintptr_t)1023);
  const uint32_t sb = smem_u32(sm);
  int* snbr = (int*)(sm + NBR_OFF);
  __shared__ float sred[128];
  const uint4* bw = (const uint4*)bswz;

  const int t   = threadIdx.x;
  const int L   = t & 31;
  const int w   = t >> 5;           // warp id 0..7, owns rows 16w..16w+15
  const int row0 = blockIdx.x * 128;

  if (t < 128) sred[t] = 0.f;

  // prefetch neighbor indices (contiguous slice)
  {
    const int* src = nbr + (size_t)row0*KN;
#pragma unroll
    for (int i = 0; i < 14; i++){
      int o = t + i*256;
      if (o < 128*KN) snbr[o] = src[o];
    }
  }
  __syncthreads();

  float acc[8][4];
#pragma unroll
  for (int nb=0;nb<8;nb++)
#pragma unroll
    for (int i=0;i<4;i++) acc[nb][i]=0.f;

  // lane-constant ldmatrix address pieces
  const int arow_l  = ((L>>3)&1)*8 + (L&7);   // 0..15
  const int a_clane = (L>>4);
  const int axor    = arow_l & 7;
  const uint32_t wbase = sb + (uint32_t)w*8192;   // warp's 4-buffer ring

  fillA(0, wbase,        w, L, snbr, hi); CP_COMMIT();
  fillA(1, wbase + 2048, w, L, snbr, hi); CP_COMMIT();
  fillA(2, wbase + 4096, w, L, snbr, hi); CP_COMMIT();

  uint32_t Bb0[16], Bb1[16];
  ldgB64(bw, 0, 0, L, Bb0);

  for (int k = 0; k < KN; k++){
    CP_WAIT2();

    if (k+3 < KN) fillA(k+3, wbase + (uint32_t)((k+3)&3)*2048, w, L, snbr, hi);
    CP_COMMIT();

    const uint32_t Arow = wbase + (uint32_t)(k&3)*2048 + (uint32_t)arow_l*128;

#pragma unroll
    for (int q=0; q<4; q++){
      uint32_t* Bcur = (q&1) ? Bb1 : Bb0;
      uint32_t* Bnxt = (q&1) ? Bb0 : Bb1;
      if (q < 3) ldgB64(bw, k, q+1, L, Bnxt);
      else       ldgB64(bw, (k+1<KN)?(k+1):k, 0, L, Bnxt);

      uint32_t Ah[4];
      ldsm_x4(Arow + (uint32_t)(((q*2 + a_clane) ^ axor)*16), Ah);

#pragma unroll
      for (int nb=0; nb<8; nb++)
        hmma(acc[nb], Ah, Bcur[2*nb], Bcur[2*nb+1]);
    }
  }

  // ---- epilogue: stores + fused per-channel stats
  {
    int r0 = row0 + w*16 + (L>>2);
#pragma unroll
    for (int nb=0;nb<8;nb++){
      int col = nb*8 + (L&3)*2;
      float* c = acc[nb];
      *(float2*)&dst[(size_t)r0*CH + col]     = make_float2(c[0], c[1]);
      *(float2*)&dst[(size_t)(r0+8)*CH + col] = make_float2(c[2], c[3]);
    }
  }
#pragma unroll
  for (int nb=0;nb<8;nb++){
    float* c = acc[nb];
    float sc0 = c[0]+c[2], sc1 = c[1]+c[3];
    float qc0 = c[0]*c[0]+c[2]*c[2], qc1 = c[1]*c[1]+c[3]*c[3];
#pragma unroll
    for (int m=4;m<32;m<<=1){
      sc0 += __shfl_xor_sync(0xFFFFFFFFu, sc0, m);
      sc1 += __shfl_xor_sync(0xFFFFFFFFu, sc1, m);
      qc0 += __shfl_xor_sync(0xFFFFFFFFu, qc0, m);
      qc1 += __shfl_xor_sync(0xFFFFFFFFu, qc1, m);
    }
    if (L < 4){
      int col = nb*8 + L*2;
      atomicAdd(&sred[col],    sc0); atomicAdd(&sred[col+1],    sc1);
      atomicAdd(&sred[64+col], qc0); atomicAdd(&sred[64+col+1], qc1);
    }
  }
  __syncthreads();
  if (t < 64){
    atomicAdd(&g_sum[layer*CH + t],   sred[t]);
    atomicAdd(&g_sumsq[layer*CH + t], sred[64+t]);
  }
}

// ---------------- BN apply + emit fp32 and/or fp16 --------------------------
__global__ void bn2_kernel(const float* __restrict__ x, const float* __restrict__ gg,
                           const float* __restrict__ bb, int relu, int layer,
                           float* __restrict__ fout,
                           __half2* __restrict__ ho){
  __shared__ float sc[64], bi[64];
  int t = threadIdx.x;
  if (t < 64){
    float m = g_sum[layer*CH + t]*(1.f/NPTS);
    float v = g_sumsq[layer*CH + t]*(1.f/NPTS) - m*m;
    float s = rsqrtf(v + 1e-5f) * gg[t];
    sc[t] = s; bi[t] = bb[t] - m*s;
  }
  __syncthreads();
  int i4 = blockIdx.x*256 + t;
  float4 v = ((const float4*)x)[i4];
  int c = (i4 & 15)*4;
  v.x = v.x*sc[c]+bi[c];     v.y = v.y*sc[c+1]+bi[c+1];
  v.z = v.z*sc[c+2]+bi[c+2]; v.w = v.w*sc[c+3]+bi[c+3];
  if (relu){ v.x=fmaxf(v.x,0.f); v.y=fmaxf(v.y,0.f); v.z=fmaxf(v.z,0.f); v.w=fmaxf(v.w,0.f); }
  if (fout) ((float4*)fout)[i4] = v;
  if (ho){
    ho[2*i4]   = __halves2half2(__float2half(v.x), __float2half(v.y));
    ho[2*i4+1] = __halves2half2(__float2half(v.z), __float2half(v.w));
  }
}

// ---------------- segment sum/max over batches (B=2), 192 channels ---------
__global__ void seg_kernel(const int* __restrict__ bidx){
  int j = threadIdx.x;
  const float* kxp = (j<64)? g_kx0 : ((j<128)? g_kx1 : g_kx2);
  int c = j & 63;
  int n0 = blockIdx.x*400, n1 = n0+400;
  float s0=0.f, s1=0.f, m0=-FLT_MAX, m1=-FLT_MAX;
  for (int n=n0;n<n1;n++){
    float v = kxp[n*CH + c];
    if (bidx[n]==0){ s0+=v; m0=fmaxf(m0,v); } else { s1+=v; m1=fmaxf(m1,v); }
  }
  atomicAdd(&g_segsum[j], s0);
  atomicAdd(&g_segsum[CAQ+j], s1);
  atomicMaxFloat(&g_segmax[j], m0);
  atomicMaxFloat(&g_segmax[CAQ+j], m1);
}

// ---------------- tiny FC + sigmoid attention ------------------------------
__global__ void fc_kernel(const int* __restrict__ bidx,
    const float* __restrict__ w1, const float* __restrict__ b1,
    const float* __restrict__ w2, const float* __restrict__ b2,
    const float* __restrict__ ksw)
{
  __shared__ float ha[NB][HID], hm[NB][HID];
  __shared__ int red[256];
  __shared__ int scnt[NB];
  int t = threadIdx.x;
  int c0 = 0;
  for (int n=t; n<NPTS; n+=256) c0 += (bidx[n]==0);
  red[t]=c0; __syncthreads();
  for (int s=128;s>0;s>>=1){ if (t<s) red[t]+=red[t+s]; __syncthreads(); }
  if (t==0){ scnt[0]=red[0]; scnt[1]=NPTS-red[0]; }
  __syncthreads();
  if (t<48){
    int which = t/24;
    int b  = (t/12)%2;
    int tt = t%12;
    float s = b1[tt];
    float inv = 1.f/(float)scnt[b];
    for (int j=0;j<CAQ;j++){
      float z = which ? g_segmax[b*CAQ+j] : g_segsum[b*CAQ+j]*inv;
      s += z * w1[j*HID+tt];
    }
    s = fmaxf(s,0.f);
    if (which) hm[b][tt]=s; else ha[b][tt]=s;
  }
  __syncthreads();
  for (int o=t; o<NB*CAQ; o+=256){
    int b=o/CAQ, j=o%CAQ;
    float sa=b2[j], sm=b2[j];
    for (int tt=0;tt<HID;tt++){ sa += ha[b][tt]*w2[tt*CAQ+j]; sm += hm[b][tt]*w2[tt*CAQ+j]; }
    float s = sa+sm;
    g_att[o] = 1.f/(1.f+expf(-s));
  }
  if (t<NXX) g_wsig[t] = 1.f/(1.f+expf(-ksw[t]));
}

// ---------------- fusion epilogue ------------------------------------------
__device__ __forceinline__ float kx_read(int sel, int off){
  return sel==0 ? g_kx0[off] : (sel==1 ? g_kx1[off] : g_kx2[off]);
}
__global__ void final_kernel(const float* __restrict__ feats,
                             const int* __restrict__ bidx,
                             float* __restrict__ out){
  int i = blockIdx.x*256 + threadIdx.x;
  int n = i >> 6, c = i & 63;
  int b = bidx[n];
  float acc = feats[i];
#pragma unroll
  for (int ii=0; ii<NXX; ii++){
    int j = 3*c + ii;
    int sel = j >> 6, col = j & 63;
    float xj  = kx_read(sel, n*CH + col);
    float kxi = kx_read(ii, i);
    acc += g_wsig[ii] * (kxi + xj * g_att[b*CAQ + j]);
  }
  out[i] = fmaxf(acc, 0.f);
}

// ---------------- launch ----------------------------------------------------
extern "C" void kernel_launch(void* const* d_in, const int* in_sizes, int n_in,
                              void* d_out, int out_size){
  (void)in_sizes; (void)n_in; (void)out_size;
  const float* feats=(const float*)d_in[0];
  const int*   bidx =(const int*)d_in[1];
  const int*   nbr  =(const int*)d_in[2];
  const float* W1 =(const float*)d_in[3];
  const float* g1 =(const float*)d_in[4];
  const float* b1 =(const float*)d_in[5];
  const float* W2 =(const float*)d_in[6];
  const float* g2 =(const float*)d_in[7];
  const float* b2 =(const float*)d_in[8];
  const float* Wk =(const float*)d_in[9];
  const float* gk =(const float*)d_in[10];
  const float* bk =(const float*)d_in[11];
  const float* fc1w=(const float*)d_in[12];
  const float* fc1b=(const float*)d_in[13];
  const float* fc2w=(const float*)d_in[14];
  const float* fc2b=(const float*)d_in[15];
  const float* ksw =(const float*)d_in[16];
  float* out=(float*)d_out;

  float *pConv,*pk0,*pk1,*pk2;
  __half2 *pHiA,*pHiB;
  uint32_t* pW;
  cudaGetSymbolAddress((void**)&pConv, g_conv);
  cudaGetSymbolAddress((void**)&pk0, g_kx0);
  cudaGetSymbolAddress((void**)&pk1, g_kx1);
  cudaGetSymbolAddress((void**)&pk2, g_kx2);
  cudaGetSymbolAddress((void**)&pHiA, g_hiA);
  cudaGetSymbolAddress((void**)&pHiB, g_hiB);
  cudaGetSymbolAddress((void**)&pW,  g_wswz);

  cudaFuncSetAttribute(conv_mma, cudaFuncAttributeMaxDynamicSharedMemorySize, SM_DYN);

  clear_all_kernel<<<2,256>>>();
  wprep_kernel<<<(5*KN*2048 + 255)/256, 256>>>(W1, W2, Wk);
  cvt_kernel<<<NPTS*CH/4/256, 256>>>((const float4*)feats, pHiA);

  struct Step {
    const __half *hi; const uint32_t* bw;
    const float *g, *b; int relu;
    float* fout; __half2 *ho;
  };
  Step steps[5] = {
    {(const __half*)pHiA, pW + 0*KN*2048, g1,      b1,      1, nullptr, pHiB},
    {(const __half*)pHiB, pW + 1*KN*2048, g2,      b2,      0, nullptr, pHiA},
    {(const __half*)pHiA, pW + 2*KN*2048, gk,      bk,      1, pk0,     pHiB},
    {(const __half*)pHiB, pW + 3*KN*2048, gk+CH,   bk+CH,   1, pk1,     pHiA},
    {(const __half*)pHiA, pW + 4*KN*2048, gk+2*CH, bk+2*CH, 1, pk2,     nullptr},
  };
  for (int s=0;s<5;s++){
    conv_mma<<<NPTS/128, 256, SM_DYN>>>(steps[s].hi, nbr, steps[s].bw, pConv, s);
    bn2_kernel<<<NPTS*CH/4/256, 256>>>(pConv, steps[s].g, steps[s].b, steps[s].relu, s,
                                       steps[s].fout, steps[s].ho);
  }
  seg_kernel<<<200, CAQ>>>(bidx);
  fc_kernel<<<1,256>>>(bidx, fc1w, fc1b, fc2w, fc2b, ksw);
  final_kernel<<<(NPTS*CH)/256, 256>>>(feats, bidx, out);
}

// round 13
// speedup vs baseline: 1.1189x; 1.1189x over previous
#include <cuda_runtime.h>
#include <cuda_fp16.h>
#include <math.h>
#include <float.h>
#include <stdint.h>

#define NPTS 80000
#define CH   64
#define KN   27
#define NB   2
#define NXX  3
#define CAQ  192
#define HID  12

// ---------------- scratch (device globals; no allocation allowed) ----------
__device__ float g_conv[NPTS*CH];
__device__ float g_kx0[NPTS*CH];
__device__ float g_kx1[NPTS*CH];
__device__ float g_kx2[NPTS*CH];
__device__ __half2 g_hiA[NPTS*CH/2];
__device__ __half2 g_hiB[NPTS*CH/2];
__device__ uint32_t g_wswz[5*KN*2048];      // W_hi fp16, mma-fragment packed (8KB/tap)
__device__ float g_sum[5*CH], g_sumsq[5*CH];
__device__ float g_segsum[NB*CAQ], g_segmax[NB*CAQ], g_att[NB*CAQ], g_wsig[NXX];

// ---------------- helpers ----------------------------------------------------
__device__ __forceinline__ uint32_t smem_u32(const void* p){
  uint32_t a;
  asm("{ .reg .u64 t; cvta.to.shared.u64 t, %1; cvt.u32.u64 %0, t; }" : "=r"(a) : "l"(p));
  return a;
}
__device__ __forceinline__ void ldsm_x4(uint32_t addr, uint32_t* r){
  asm volatile("ldmatrix.sync.aligned.m8n8.x4.shared.b16 {%0,%1,%2,%3}, [%4];"
    : "=r"(r[0]),"=r"(r[1]),"=r"(r[2]),"=r"(r[3]) : "r"(addr));
}
__device__ __forceinline__ void hmma(float* c, const uint32_t* a, uint32_t b0, uint32_t b1){
  asm volatile(
    "mma.sync.aligned.m16n8k16.row.col.f32.f16.f16.f32 "
    "{%0,%1,%2,%3}, {%4,%5,%6,%7}, {%8,%9}, {%0,%1,%2,%3};"
    : "+f"(c[0]), "+f"(c[1]), "+f"(c[2]), "+f"(c[3])
    : "r"(a[0]), "r"(a[1]), "r"(a[2]), "r"(a[3]), "r"(b0), "r"(b1));
}
__device__ __forceinline__ void cp16z(uint32_t sdst, const void* gsrc, int srcsz){
  asm volatile("cp.async.cg.shared.global [%0], [%1], 16, %2;" :: "r"(sdst), "l"(gsrc), "r"(srcsz));
}
#define CP_COMMIT() asm volatile("cp.async.commit_group;" ::: "memory")
#define CP_WAIT2()  asm volatile("cp.async.wait_group 2;" ::: "memory")
#define PAIR_BAR(id) asm volatile("bar.sync %0, 64;" :: "r"(id) : "memory")

__device__ __forceinline__ void atomicMaxFloat(float* addr, float val){
  int* ai = (int*)addr;
  int old = *ai;
  while (true){
    float fo = __int_as_float(old);
    if (fo >= val) break;
    int assumed = old;
    old = atomicCAS(ai, assumed, __float_as_int(val));
    if (old == assumed) break;
  }
}

// ---------------- weight prep: pack W_hi into mma B-fragment order ----------
__global__ void wprep_kernel(const float* __restrict__ W1,
                             const float* __restrict__ W2,
                             const float* __restrict__ Wk){
  int gid = blockIdx.x*256 + threadIdx.x;
  if (gid >= 5*KN*2048) return;
  int slot = gid & 2047;
  int tk = gid >> 11;
  int l = tk/KN, k = tk - l*KN;
  const float* Ws = (l==0)? W1 : (l==1)? W2 : (Wk + (size_t)(l-2)*KN*CH*CH);
  int r    = slot & 3;
  int L    = (slot >> 2) & 31;
  int rest = slot >> 7;
  int quad = rest & 1;
  int q    = (rest >> 1) & 3;
  int wn   = rest >> 3;
  int n  = wn*32 + quad*16 + (r>>1)*8 + (L>>2);
  int kk = q*16 + (L&3)*2 + (r&1)*8;
  __half b0 = __float2half(Ws[k*CH*CH + kk*CH + n]);
  __half b1 = __float2half(Ws[k*CH*CH + (kk+1)*CH + n]);
  g_wswz[tk*2048 + slot] =
      (uint32_t)__half_as_ushort(b0) | ((uint32_t)__half_as_ushort(b1) << 16);
}

// ---------------- fp32 -> fp16 conversion of layer-0 input ------------------
__global__ void cvt_kernel(const float4* __restrict__ x,
                           __half2* __restrict__ ho){
  int i4 = blockIdx.x*256 + threadIdx.x;
  float4 v = x[i4];
  ho[2*i4]   = __halves2half2(__float2half(v.x), __float2half(v.y));
  ho[2*i4+1] = __halves2half2(__float2half(v.z), __float2half(v.w));
}

// ---------------- one-shot clears (stats x5 layers + segment buffers) -------
__global__ void clear_all_kernel(){
  int t = blockIdx.x*256 + threadIdx.x;
  if (t < 5*CH){ g_sum[t]=0.f; g_sumsq[t]=0.f; }
  if (t < NB*CAQ){ g_segsum[t]=0.f; g_segmax[t]=-FLT_MAX; }
}

// ---------------- HMMA gathered conv (R10 structure, quad-buffered) ----------
// Single-pass fp16. Pair tiling: 4 row-pairs (wm) x 2 col-halves (wn).
// A: smem 128 rows x 128B, QUAD-buffered (64KB), 1 pair-bar/tap, wait_group 2.
// B: registers via LDG.128 (fragment-packed gmem, L1/L2-hot), per-q dbl buffer.
#define NBR_OFF 65536
#define SM_DYN (65536 + 13824 + 1024)

__device__ __forceinline__ void ldgB(const uint4* __restrict__ bw,
                                     int k, int q, int wn, int L, uint32_t* B){
  const uint4* p = bw + (size_t)k*512 + (size_t)((wn*4 + q)*2)*32 + L;
  uint4 v0 = __ldg(p);
  uint4 v1 = __ldg(p + 32);
  B[0]=v0.x; B[1]=v0.y; B[2]=v0.z; B[3]=v0.w;
  B[4]=v1.x; B[5]=v1.y; B[6]=v1.z; B[7]=v1.w;
}

// A fill (R10 form): thread t -> row t>>1, half (t&1) = 4 chunks of 16B
__device__ __forceinline__ void fillA(
    int k, int buf, int t, uint32_t sb, const int* __restrict__ snbr,
    const __half* __restrict__ hi)
{
  int r = (t>>6)*32 + ((t&63)>>1);   // pair-local rows
  int half = t & 1;
  int idx = snbr[r*KN + k];
  int sz = idx>=0 ? 16 : 0;
  int sidx = idx>=0 ? idx : 0;
  const char* asrc = (const char*)(hi + (size_t)sidx*CH);
  uint32_t rbase = sb + (uint32_t)buf*16384 + (uint32_t)r*128;
  int xr = r & 7;
#pragma unroll
  for (int j=0;j<4;j++){
    int c = half*4 + j;
    int sw = c ^ xr;
    cp16z(rbase + sw*16, asrc + c*16, sz);
  }
}

__global__ void __launch_bounds__(256,2) conv_mma(
    const __half* __restrict__ hi,
    const int* __restrict__ nbr, const uint32_t* __restrict__ bswz,
    float* __restrict__ dst, int layer)
{
  extern __shared__ char smraw[];
  char* sm = (char*)(((uintptr_t)smraw + 1023) & ~(uintptr_t)1023);
  const uint32_t sb = smem_u32(sm);
  int* snbr = (int*)(sm + NBR_OFF);
  __shared__ float sred[128];
  const uint4* bw = (const uint4*)bswz;

  const int t   = threadIdx.x;
  const int L   = t & 31;
  const int wid = t >> 5;
  const int wm  = wid >> 1;
  const int wn  = wid & 1;
  const int row0 = blockIdx.x * 128;
  const int barid = 1 + wm;

  if (t < 128) sred[t] = 0.f;

  // prefetch neighbor indices (contiguous slice)
  {
    const int* src = nbr + (size_t)row0*KN;
#pragma unroll
    for (int i = 0; i < 14; i++){
      int o = t + i*256;
      if (o < 128*KN) snbr[o] = src[o];
    }
  }
  __syncthreads();

  float acc[2][4][4];
#pragma unroll
  for (int s=0;s<2;s++)
#pragma unroll
    for (int nb=0;nb<4;nb++)
#pragma unroll
      for (int i=0;i<4;i++) acc[s][nb][i]=0.f;

  // lane-constant ldmatrix address pieces (A only)
  const int arow_l  = ((L>>3)&1)*8 + (L&7);
  const int a_clane = (L>>4);
  const int arow    = wm*32 + arow_l;
  const int axor    = arow & 7;

  fillA(0, 0, t, sb, snbr, hi); CP_COMMIT();
  fillA(1, 1, t, sb, snbr, hi); CP_COMMIT();
  fillA(2, 2, t, sb, snbr, hi); CP_COMMIT();

  uint32_t Bb0[8], Bb1[8];
  ldgB(bw, 0, 0, wn, L, Bb0);

  for (int k = 0; k < KN; k++){
    CP_WAIT2();
    PAIR_BAR(barid);

    if (k+3 < KN) fillA(k+3, (k+3)&3, t, sb, snbr, hi);
    CP_COMMIT();

    const uint32_t Arow = sb + (uint32_t)(k&3)*16384 + (uint32_t)arow*128;

#pragma unroll
    for (int q=0; q<4; q++){
      uint32_t* Bcur = (q&1) ? Bb1 : Bb0;
      uint32_t* Bnxt = (q&1) ? Bb0 : Bb1;
      if (q < 3) ldgB(bw, k, q+1, wn, L, Bnxt);
      else       ldgB(bw, (k+1<KN)?(k+1):k, 0, wn, L, Bnxt);

      uint32_t Ah0[4], Ah1[4];
      uint32_t ah = Arow + (uint32_t)(((q*2 + a_clane) ^ axor)*16);
      ldsm_x4(ah, Ah0);
      ldsm_x4(ah + 16*128, Ah1);

      hmma(acc[0][0], Ah0, Bcur[0], Bcur[1]);
      hmma(acc[0][1], Ah0, Bcur[2], Bcur[3]);
      hmma(acc[0][2], Ah0, Bcur[4], Bcur[5]);
      hmma(acc[0][3], Ah0, Bcur[6], Bcur[7]);
      hmma(acc[1][0], Ah1, Bcur[0], Bcur[1]);
      hmma(acc[1][1], Ah1, Bcur[2], Bcur[3]);
      hmma(acc[1][2], Ah1, Bcur[4], Bcur[5]);
      hmma(acc[1][3], Ah1, Bcur[6], Bcur[7]);
    }
  }

  // ---- epilogue: stores + fused per-channel stats
#pragma unroll
  for (int s=0;s<2;s++){
    int r = row0 + wm*32 + s*16 + (L>>2);
#pragma unroll
    for (int nb=0;nb<4;nb++){
      int col = wn*32 + nb*8 + (L&3)*2;
      float* c = acc[s][nb];
      *(float2*)&dst[(size_t)r*CH + col]     = make_float2(c[0], c[1]);
      *(float2*)&dst[(size_t)(r+8)*CH + col] = make_float2(c[2], c[3]);
    }
  }
#pragma unroll
  for (int nb=0;nb<4;nb++){
    float sc0=0.f, sc1=0.f, qc0=0.f, qc1=0.f;
#pragma unroll
    for (int s=0;s<2;s++){
      float* c = acc[s][nb];
      sc0 += c[0]+c[2]; qc0 += c[0]*c[0]+c[2]*c[2];
      sc1 += c[1]+c[3]; qc1 += c[1]*c[1]+c[3]*c[3];
    }
#pragma unroll
    for (int m=4;m<32;m<<=1){
      sc0 += __shfl_xor_sync(0xFFFFFFFFu, sc0, m);
      sc1 += __shfl_xor_sync(0xFFFFFFFFu, sc1, m);
      qc0 += __shfl_xor_sync(0xFFFFFFFFu, qc0, m);
      qc1 += __shfl_xor_sync(0xFFFFFFFFu, qc1, m);
    }
    if (L < 4){
      int col = wn*32 + nb*8 + L*2;
      atomicAdd(&sred[col],    sc0); atomicAdd(&sred[col+1],    sc1);
      atomicAdd(&sred[64+col], qc0); atomicAdd(&sred[64+col+1], qc1);
    }
  }
  __syncthreads();
  if (t < 64){
    atomicAdd(&g_sum[layer*CH + t],   sred[t]);
    atomicAdd(&g_sumsq[layer*CH + t], sred[64+t]);
  }
}

// ---------------- BN apply + emit fp32 and/or fp16 --------------------------
__global__ void bn2_kernel(const float* __restrict__ x, const float* __restrict__ gg,
                           const float* __restrict__ bb, int relu, int layer,
                           float* __restrict__ fout,
                           __half2* __restrict__ ho){
  __shared__ float sc[64], bi[64];
  int t = threadIdx.x;
  if (t < 64){
    float m = g_sum[layer*CH + t]*(1.f/NPTS);
    float v = g_sumsq[layer*CH + t]*(1.f/NPTS) - m*m;
    float s = rsqrtf(v + 1e-5f) * gg[t];
    sc[t] = s; bi[t] = bb[t] - m*s;
  }
  __syncthreads();
  int i4 = blockIdx.x*256 + t;
  float4 v = ((const float4*)x)[i4];
  int c = (i4 & 15)*4;
  v.x = v.x*sc[c]+bi[c];     v.y = v.y*sc[c+1]+bi[c+1];
  v.z = v.z*sc[c+2]+bi[c+2]; v.w = v.w*sc[c+3]+bi[c+3];
  if (relu){ v.x=fmaxf(v.x,0.f); v.y=fmaxf(v.y,0.f); v.z=fmaxf(v.z,0.f); v.w=fmaxf(v.w,0.f); }
  if (fout) ((float4*)fout)[i4] = v;
  if (ho){
    ho[2*i4]   = __halves2half2(__float2half(v.x), __float2half(v.y));
    ho[2*i4+1] = __halves2half2(__float2half(v.z), __float2half(v.w));
  }
}

// ---------------- segment sum/max over batches (B=2), 192 channels ---------
__global__ void seg_kernel(const int* __restrict__ bidx){
  int j = threadIdx.x;
  const float* kxp = (j<64)? g_kx0 : ((j<128)? g_kx1 : g_kx2);
  int c = j & 63;
  int n0 = blockIdx.x*200, n1 = n0+200;
  float s0=0.f, s1=0.f, m0=-FLT_MAX, m1=-FLT_MAX;
  for (int n=n0;n<n1;n++){
    float v = kxp[n*CH + c];
    if (bidx[n]==0){ s0+=v; m0=fmaxf(m0,v); } else { s1+=v; m1=fmaxf(m1,v); }
  }
  atomicAdd(&g_segsum[j], s0);
  atomicAdd(&g_segsum[CAQ+j], s1);
  atomicMaxFloat(&g_segmax[j], m0);
  atomicMaxFloat(&g_segmax[CAQ+j], m1);
}

// ---------------- tiny FC + sigmoid attention ------------------------------
__global__ void fc_kernel(const int* __restrict__ bidx,
    const float* __restrict__ w1, const float* __restrict__ b1,
    const float* __restrict__ w2, const float* __restrict__ b2,
    const float* __restrict__ ksw)
{
  __shared__ float ha[NB][HID], hm[NB][HID];
  __shared__ int red[256];
  __shared__ int scnt[NB];
  int t = threadIdx.x;
  int c0 = 0;
  for (int n=t; n<NPTS; n+=256) c0 += (bidx[n]==0);
  red[t]=c0; __syncthreads();
  for (int s=128;s>0;s>>=1){ if (t<s) red[t]+=red[t+s]; __syncthreads(); }
  if (t==0){ scnt[0]=red[0]; scnt[1]=NPTS-red[0]; }
  __syncthreads();
  if (t<48){
    int which = t/24;
    int b  = (t/12)%2;
    int tt = t%12;
    float s = b1[tt];
    float inv = 1.f/(float)scnt[b];
    for (int j=0;j<CAQ;j++){
      float z = which ? g_segmax[b*CAQ+j] : g_segsum[b*CAQ+j]*inv;
      s += z * w1[j*HID+tt];
    }
    s = fmaxf(s,0.f);
    if (which) hm[b][tt]=s; else ha[b][tt]=s;
  }
  __syncthreads();
  for (int o=t; o<NB*CAQ; o+=256){
    int b=o/CAQ, j=o%CAQ;
    float sa=b2[j], sm=b2[j];
    for (int tt=0;tt<HID;tt++){ sa += ha[b][tt]*w2[tt*CAQ+j]; sm += hm[b][tt]*w2[tt*CAQ+j]; }
    float s = sa+sm;
    g_att[o] = 1.f/(1.f+expf(-s));
  }
  if (t<NXX) g_wsig[t] = 1.f/(1.f+expf(-ksw[t]));
}

// ---------------- fusion epilogue ------------------------------------------
__device__ __forceinline__ float kx_read(int sel, int off){
  return sel==0 ? g_kx0[off] : (sel==1 ? g_kx1[off] : g_kx2[off]);
}
__global__ void final_kernel(const float* __restrict__ feats,
                             const int* __restrict__ bidx,
                             float* __restrict__ out){
  int i = blockIdx.x*256 + threadIdx.x;
  int n = i >> 6, c = i & 63;
  int b = bidx[n];
  float acc = feats[i];
#pragma unroll
  for (int ii=0; ii<NXX; ii++){
    int j = 3*c + ii;
    int sel = j >> 6, col = j & 63;
    float xj  = kx_read(sel, n*CH + col);
    float kxi = kx_read(ii, i);
    acc += g_wsig[ii] * (kxi + xj * g_att[b*CAQ + j]);
  }
  out[i] = fmaxf(acc, 0.f);
}

// ---------------- launch ----------------------------------------------------
extern "C" void kernel_launch(void* const* d_in, const int* in_sizes, int n_in,
                              void* d_out, int out_size){
  (void)in_sizes; (void)n_in; (void)out_size;
  const float* feats=(const float*)d_in[0];
  const int*   bidx =(const int*)d_in[1];
  const int*   nbr  =(const int*)d_in[2];
  const float* W1 =(const float*)d_in[3];
  const float* g1 =(const float*)d_in[4];
  const float* b1 =(const float*)d_in[5];
  const float* W2 =(const float*)d_in[6];
  const float* g2 =(const float*)d_in[7];
  const float* b2 =(const float*)d_in[8];
  const float* Wk =(const float*)d_in[9];
  const float* gk =(const float*)d_in[10];
  const float* bk =(const float*)d_in[11];
  const float* fc1w=(const float*)d_in[12];
  const float* fc1b=(const float*)d_in[13];
  const float* fc2w=(const float*)d_in[14];
  const float* fc2b=(const float*)d_in[15];
  const float* ksw =(const float*)d_in[16];
  float* out=(float*)d_out;

  float *pConv,*pk0,*pk1,*pk2;
  __half2 *pHiA,*pHiB;
  uint32_t* pW;
  cudaGetSymbolAddress((void**)&pConv, g_conv);
  cudaGetSymbolAddress((void**)&pk0, g_kx0);
  cudaGetSymbolAddress((void**)&pk1, g_kx1);
  cudaGetSymbolAddress((void**)&pk2, g_kx2);
  cudaGetSymbolAddress((void**)&pHiA, g_hiA);
  cudaGetSymbolAddress((void**)&pHiB, g_hiB);
  cudaGetSymbolAddress((void**)&pW,  g_wswz);

  cudaFuncSetAttribute(conv_mma, cudaFuncAttributeMaxDynamicSharedMemorySize, SM_DYN);

  clear_all_kernel<<<2,256>>>();
  wprep_kernel<<<(5*KN*2048 + 255)/256, 256>>>(W1, W2, Wk);
  cvt_kernel<<<NPTS*CH/4/256, 256>>>((const float4*)feats, pHiA);

  struct Step {
    const __half *hi; const uint32_t* bw;
    const float *g, *b; int relu;
    float* fout; __half2 *ho;
  };
  Step steps[5] = {
    {(const __half*)pHiA, pW + 0*KN*2048, g1,      b1,      1, nullptr, pHiB},
    {(const __half*)pHiB, pW + 1*KN*2048, g2,      b2,      0, nullptr, pHiA},
    {(const __half*)pHiA, pW + 2*KN*2048, gk,      bk,      1, pk0,     pHiB},
    {(const __half*)pHiB, pW + 3*KN*2048, gk+CH,   bk+CH,   1, pk1,     pHiA},
    {(const __half*)pHiA, pW + 4*KN*2048, gk+2*CH, bk+2*CH, 1, pk2,     nullptr},
  };
  for (int s=0;s<5;s++){
    conv_mma<<<NPTS/128, 256, SM_DYN>>>(steps[s].hi, nbr, steps[s].bw, pConv, s);
    bn2_kernel<<<NPTS*CH/4/256, 256>>>(pConv, steps[s].g, steps[s].b, steps[s].relu, s,
                                       steps[s].fout, steps[s].ho);
  }
  seg_kernel<<<400, CAQ>>>(bidx);
  fc_kernel<<<1,256>>>(bidx, fc1w, fc1b, fc2w, fc2b, ksw);
  final_kernel<<<(NPTS*CH)/256, 256>>>(feats, bidx, out);
}

// round 14
// speedup vs baseline: 1.1353x; 1.0146x over previous
#include <cuda_runtime.h>
#include <cuda_fp16.h>
#include <math.h>
#include <float.h>
#include <stdint.h>

#define NPTS 80000
#define CH   64
#define KN   27
#define NB   2
#define NXX  3
#define CAQ  192
#define HID  12
#define NTILES 625
#define GRIDC  592   // 2 * 296 co-resident slots; first 33 CTAs take 2 tiles

// ---------------- scratch (device globals; no allocation allowed) ----------
__device__ float g_conv[NPTS*CH];
__device__ float g_kx0[NPTS*CH];
__device__ float g_kx1[NPTS*CH];
__device__ float g_kx2[NPTS*CH];
__device__ __half2 g_hiA[NPTS*CH/2];
__device__ __half2 g_hiB[NPTS*CH/2];
__device__ uint32_t g_wswz[5*KN*2048];      // W_hi fp16, mma-fragment packed (8KB/tap)
__device__ float g_sum[5*CH], g_sumsq[5*CH];
__device__ float g_segsum[NB*CAQ], g_segmax[NB*CAQ], g_att[NB*CAQ], g_wsig[NXX];

// ---------------- helpers ----------------------------------------------------
__device__ __forceinline__ uint32_t smem_u32(const void* p){
  uint32_t a;
  asm("{ .reg .u64 t; cvta.to.shared.u64 t, %1; cvt.u32.u64 %0, t; }" : "=r"(a) : "l"(p));
  return a;
}
__device__ __forceinline__ void ldsm_x4(uint32_t addr, uint32_t* r){
  asm volatile("ldmatrix.sync.aligned.m8n8.x4.shared.b16 {%0,%1,%2,%3}, [%4];"
    : "=r"(r[0]),"=r"(r[1]),"=r"(r[2]),"=r"(r[3]) : "r"(addr));
}
__device__ __forceinline__ void hmma(float* c, const uint32_t* a, uint32_t b0, uint32_t b1){
  asm volatile(
    "mma.sync.aligned.m16n8k16.row.col.f32.f16.f16.f32 "
    "{%0,%1,%2,%3}, {%4,%5,%6,%7}, {%8,%9}, {%0,%1,%2,%3};"
    : "+f"(c[0]), "+f"(c[1]), "+f"(c[2]), "+f"(c[3])
    : "r"(a[0]), "r"(a[1]), "r"(a[2]), "r"(a[3]), "r"(b0), "r"(b1));
}
__device__ __forceinline__ void cp16z(uint32_t sdst, const void* gsrc, int srcsz){
  asm volatile("cp.async.cg.shared.global [%0], [%1], 16, %2;" :: "r"(sdst), "l"(gsrc), "r"(srcsz));
}
#define CP_COMMIT() asm volatile("cp.async.commit_group;" ::: "memory")
#define CP_WAIT2()  asm volatile("cp.async.wait_group 2;" ::: "memory")
#define PAIR_BAR(id) asm volatile("bar.sync %0, 64;" :: "r"(id) : "memory")

__device__ __forceinline__ void atomicMaxFloat(float* addr, float val){
  int* ai = (int*)addr;
  int old = *ai;
  while (true){
    float fo = __int_as_float(old);
    if (fo >= val) break;
    int assumed = old;
    old = atomicCAS(ai, assumed, __float_as_int(val));
    if (old == assumed) break;
  }
}

// ---------------- weight prep: pack W_hi into mma B-fragment order ----------
__global__ void wprep_kernel(const float* __restrict__ W1,
                             const float* __restrict__ W2,
                             const float* __restrict__ Wk){
  int gid = blockIdx.x*256 + threadIdx.x;
  if (gid >= 5*KN*2048) return;
  int slot = gid & 2047;
  int tk = gid >> 11;
  int l = tk/KN, k = tk - l*KN;
  const float* Ws = (l==0)? W1 : (l==1)? W2 : (Wk + (size_t)(l-2)*KN*CH*CH);
  int r    = slot & 3;
  int L    = (slot >> 2) & 31;
  int rest = slot >> 7;
  int quad = rest & 1;
  int q    = (rest >> 1) & 3;
  int wn   = rest >> 3;
  int n  = wn*32 + quad*16 + (r>>1)*8 + (L>>2);
  int kk = q*16 + (L&3)*2 + (r&1)*8;
  __half b0 = __float2half(Ws[k*CH*CH + kk*CH + n]);
  __half b1 = __float2half(Ws[k*CH*CH + (kk+1)*CH + n]);
  g_wswz[tk*2048 + slot] =
      (uint32_t)__half_as_ushort(b0) | ((uint32_t)__half_as_ushort(b1) << 16);
}

// ---------------- fp32 -> fp16 conversion of layer-0 input ------------------
__global__ void cvt_kernel(const float4* __restrict__ x,
                           __half2* __restrict__ ho){
  int i4 = blockIdx.x*256 + threadIdx.x;
  float4 v = x[i4];
  ho[2*i4]   = __halves2half2(__float2half(v.x), __float2half(v.y));
  ho[2*i4+1] = __halves2half2(__float2half(v.z), __float2half(v.w));
}

// ---------------- one-shot clears (stats x5 layers + segment buffers) -------
__global__ void clear_all_kernel(){
  int t = blockIdx.x*256 + threadIdx.x;
  if (t < 5*CH){ g_sum[t]=0.f; g_sumsq[t]=0.f; }
  if (t < NB*CAQ){ g_segsum[t]=0.f; g_segmax[t]=-FLT_MAX; }
}

// ---------------- HMMA gathered conv ------------------------------------------
// Single-pass fp16, R13 body, grid=592 with 33 CTAs doing a 2nd tile (tail fix).
#define NBR_OFF 65536
#define SM_DYN (65536 + 13824 + 1024)

__device__ __forceinline__ void ldgB(const uint4* __restrict__ bw,
                                     int k, int q, int wn, int L, uint32_t* B){
  const uint4* p = bw + (size_t)k*512 + (size_t)((wn*4 + q)*2)*32 + L;
  uint4 v0 = __ldg(p);
  uint4 v1 = __ldg(p + 32);
  B[0]=v0.x; B[1]=v0.y; B[2]=v0.z; B[3]=v0.w;
  B[4]=v1.x; B[5]=v1.y; B[6]=v1.z; B[7]=v1.w;
}

__device__ __forceinline__ void fillA(
    int k, int buf, int t, uint32_t sb, const int* __restrict__ snbr,
    const __half* __restrict__ hi)
{
  int r = (t>>6)*32 + ((t&63)>>1);   // pair-local rows
  int half = t & 1;
  int idx = snbr[r*KN + k];
  int sz = idx>=0 ? 16 : 0;
  int sidx = idx>=0 ? idx : 0;
  const char* asrc = (const char*)(hi + (size_t)sidx*CH);
  uint32_t rbase = sb + (uint32_t)buf*16384 + (uint32_t)r*128;
  int xr = r & 7;
#pragma unroll
  for (int j=0;j<4;j++){
    int c = half*4 + j;
    int sw = c ^ xr;
    cp16z(rbase + sw*16, asrc + c*16, sz);
  }
}

__global__ void __launch_bounds__(256,2) conv_mma(
    const __half* __restrict__ hi,
    const int* __restrict__ nbr, const uint32_t* __restrict__ bswz,
    float* __restrict__ dst, int layer)
{
  extern __shared__ char smraw[];
  char* sm = (char*)(((uintptr_t)smraw + 1023) & ~(uintptr_t)1023);
  const uint32_t sb = smem_u32(sm);
  int* snbr = (int*)(sm + NBR_OFF);
  __shared__ float sred[128];
  const uint4* bw = (const uint4*)bswz;

  const int t   = threadIdx.x;
  const int L   = t & 31;
  const int wid = t >> 5;
  const int wm  = wid >> 1;
  const int wn  = wid & 1;
  const int barid = 1 + wm;

  // lane-constant ldmatrix address pieces (A only)
  const int arow_l  = ((L>>3)&1)*8 + (L&7);
  const int a_clane = (L>>4);
  const int arow    = wm*32 + arow_l;
  const int axor    = arow & 7;

  for (int tile = blockIdx.x; tile < NTILES; tile += GRIDC){
    const int row0 = tile * 128;

    if (t < 128) sred[t] = 0.f;

    // prefetch neighbor indices (contiguous slice)
    {
      const int* src = nbr + (size_t)row0*KN;
#pragma unroll
      for (int i = 0; i < 14; i++){
        int o = t + i*256;
        if (o < 128*KN) snbr[o] = src[o];
      }
    }
    __syncthreads();

    float acc[2][4][4];
#pragma unroll
    for (int s=0;s<2;s++)
#pragma unroll
      for (int nb=0;nb<4;nb++)
#pragma unroll
        for (int i=0;i<4;i++) acc[s][nb][i]=0.f;

    fillA(0, 0, t, sb, snbr, hi); CP_COMMIT();
    fillA(1, 1, t, sb, snbr, hi); CP_COMMIT();
    fillA(2, 2, t, sb, snbr, hi); CP_COMMIT();

    uint32_t Bb0[8], Bb1[8];
    ldgB(bw, 0, 0, wn, L, Bb0);

    for (int k = 0; k < KN; k++){
      CP_WAIT2();
      PAIR_BAR(barid);

      if (k+3 < KN) fillA(k+3, (k+3)&3, t, sb, snbr, hi);
      CP_COMMIT();

      const uint32_t Arow = sb + (uint32_t)(k&3)*16384 + (uint32_t)arow*128;

#pragma unroll
      for (int q=0; q<4; q++){
        uint32_t* Bcur = (q&1) ? Bb1 : Bb0;
        uint32_t* Bnxt = (q&1) ? Bb0 : Bb1;
        if (q < 3) ldgB(bw, k, q+1, wn, L, Bnxt);
        else       ldgB(bw, (k+1<KN)?(k+1):k, 0, wn, L, Bnxt);

        uint32_t Ah0[4], Ah1[4];
        uint32_t ah = Arow + (uint32_t)(((q*2 + a_clane) ^ axor)*16);
        ldsm_x4(ah, Ah0);
        ldsm_x4(ah + 16*128, Ah1);

        hmma(acc[0][0], Ah0, Bcur[0], Bcur[1]);
        hmma(acc[0][1], Ah0, Bcur[2], Bcur[3]);
        hmma(acc[0][2], Ah0, Bcur[4], Bcur[5]);
        hmma(acc[0][3], Ah0, Bcur[6], Bcur[7]);
        hmma(acc[1][0], Ah1, Bcur[0], Bcur[1]);
        hmma(acc[1][1], Ah1, Bcur[2], Bcur[3]);
        hmma(acc[1][2], Ah1, Bcur[4], Bcur[5]);
        hmma(acc[1][3], Ah1, Bcur[6], Bcur[7]);
      }
    }

    // ---- epilogue: stores + fused per-channel stats
#pragma unroll
    for (int s=0;s<2;s++){
      int r = row0 + wm*32 + s*16 + (L>>2);
#pragma unroll
      for (int nb=0;nb<4;nb++){
        int col = wn*32 + nb*8 + (L&3)*2;
        float* c = acc[s][nb];
        *(float2*)&dst[(size_t)r*CH + col]     = make_float2(c[0], c[1]);
        *(float2*)&dst[(size_t)(r+8)*CH + col] = make_float2(c[2], c[3]);
      }
    }
#pragma unroll
    for (int nb=0;nb<4;nb++){
      float sc0=0.f, sc1=0.f, qc0=0.f, qc1=0.f;
#pragma unroll
      for (int s=0;s<2;s++){
        float* c = acc[s][nb];
        sc0 += c[0]+c[2]; qc0 += c[0]*c[0]+c[2]*c[2];
        sc1 += c[1]+c[3]; qc1 += c[1]*c[1]+c[3]*c[3];
      }
#pragma unroll
      for (int m=4;m<32;m<<=1){
        sc0 += __shfl_xor_sync(0xFFFFFFFFu, sc0, m);
        sc1 += __shfl_xor_sync(0xFFFFFFFFu, sc1, m);
        qc0 += __shfl_xor_sync(0xFFFFFFFFu, qc0, m);
        qc1 += __shfl_xor_sync(0xFFFFFFFFu, qc1, m);
      }
      if (L < 4){
        int col = wn*32 + nb*8 + L*2;
        atomicAdd(&sred[col],    sc0); atomicAdd(&sred[col+1],    sc1);
        atomicAdd(&sred[64+col], qc0); atomicAdd(&sred[64+col+1], qc1);
      }
    }
    __syncthreads();
    if (t < 64){
      atomicAdd(&g_sum[layer*CH + t],   sred[t]);
      atomicAdd(&g_sumsq[layer*CH + t], sred[64+t]);
    }
    __syncthreads();   // sred reuse / smem buffer reuse across tiles
  }
}

// ---------------- BN apply + emit fp32 and/or fp16 --------------------------
__global__ void bn2_kernel(const float* __restrict__ x, const float* __restrict__ gg,
                           const float* __restrict__ bb, int relu, int layer,
                           float* __restrict__ fout,
                           __half2* __restrict__ ho){
  __shared__ float sc[64], bi[64];
  int t = threadIdx.x;
  if (t < 64){
    float m = g_sum[layer*CH + t]*(1.f/NPTS);
    float v = g_sumsq[layer*CH + t]*(1.f/NPTS) - m*m;
    float s = rsqrtf(v + 1e-5f) * gg[t];
    sc[t] = s; bi[t] = bb[t] - m*s;
  }
  __syncthreads();
  int i4 = blockIdx.x*256 + t;
  float4 v = ((const float4*)x)[i4];
  int c = (i4 & 15)*4;
  v.x = v.x*sc[c]+bi[c];     v.y = v.y*sc[c+1]+bi[c+1];
  v.z = v.z*sc[c+2]+bi[c+2]; v.w = v.w*sc[c+3]+bi[c+3];
  if (relu){ v.x=fmaxf(v.x,0.f); v.y=fmaxf(v.y,0.f); v.z=fmaxf(v.z,0.f); v.w=fmaxf(v.w,0.f); }
  if (fout) ((float4*)fout)[i4] = v;
  if (ho){
    ho[2*i4]   = __halves2half2(__float2half(v.x), __float2half(v.y));
    ho[2*i4+1] = __halves2half2(__float2half(v.z), __float2half(v.w));
  }
}

// ---------------- segment sum/max over batches (B=2), 192 channels ---------
__global__ void seg_kernel(const int* __restrict__ bidx){
  int j = threadIdx.x;
  const float* kxp = (j<64)? g_kx0 : ((j<128)? g_kx1 : g_kx2);
  int c = j & 63;
  int n0 = blockIdx.x*200, n1 = n0+200;
  float s0=0.f, s1=0.f, m0=-FLT_MAX, m1=-FLT_MAX;
  for (int n=n0;n<n1;n++){
    float v = kxp[n*CH + c];
    if (bidx[n]==0){ s0+=v; m0=fmaxf(m0,v); } else { s1+=v; m1=fmaxf(m1,v); }
  }
  atomicAdd(&g_segsum[j], s0);
  atomicAdd(&g_segsum[CAQ+j], s1);
  atomicMaxFloat(&g_segmax[j], m0);
  atomicMaxFloat(&g_segmax[CAQ+j], m1);
}

// ---------------- tiny FC + sigmoid attention ------------------------------
__global__ void fc_kernel(const int* __restrict__ bidx,
    const float* __restrict__ w1, const float* __restrict__ b1,
    const float* __restrict__ w2, const float* __restrict__ b2,
    const float* __restrict__ ksw)
{
  __shared__ float ha[NB][HID], hm[NB][HID];
  __shared__ int red[256];
  __shared__ int scnt[NB];
  int t = threadIdx.x;
  int c0 = 0;
  for (int n=t; n<NPTS; n+=256) c0 += (bidx[n]==0);
  red[t]=c0; __syncthreads();
  for (int s=128;s>0;s>>=1){ if (t<s) red[t]+=red[t+s]; __syncthreads(); }
  if (t==0){ scnt[0]=red[0]; scnt[1]=NPTS-red[0]; }
  __syncthreads();
  if (t<48){
    int which = t/24;
    int b  = (t/12)%2;
    int tt = t%12;
    float s = b1[tt];
    float inv = 1.f/(float)scnt[b];
    for (int j=0;j<CAQ;j++){
      float z = which ? g_segmax[b*CAQ+j] : g_segsum[b*CAQ+j]*inv;
      s += z * w1[j*HID+tt];
    }
    s = fmaxf(s,0.f);
    if (which) hm[b][tt]=s; else ha[b][tt]=s;
  }
  __syncthreads();
  for (int o=t; o<NB*CAQ; o+=256){
    int b=o/CAQ, j=o%CAQ;
    float sa=b2[j], sm=b2[j];
    for (int tt=0;tt<HID;tt++){ sa += ha[b][tt]*w2[tt*CAQ+j]; sm += hm[b][tt]*w2[tt*CAQ+j]; }
    float s = sa+sm;
    g_att[o] = 1.f/(1.f+expf(-s));
  }
  if (t<NXX) g_wsig[t] = 1.f/(1.f+expf(-ksw[t]));
}

// ---------------- fusion epilogue ------------------------------------------
__device__ __forceinline__ float kx_read(int sel, int off){
  return sel==0 ? g_kx0[off] : (sel==1 ? g_kx1[off] : g_kx2[off]);
}
__global__ void final_kernel(const float* __restrict__ feats,
                             const int* __restrict__ bidx,
                             float* __restrict__ out){
  int i = blockIdx.x*256 + threadIdx.x;
  int n = i >> 6, c = i & 63;
  int b = bidx[n];
  float acc = feats[i];
#pragma unroll
  for (int ii=0; ii<NXX; ii++){
    int j = 3*c + ii;
    int sel = j >> 6, col = j & 63;
    float xj  = kx_read(sel, n*CH + col);
    float kxi = kx_read(ii, i);
    acc += g_wsig[ii] * (kxi + xj * g_att[b*CAQ + j]);
  }
  out[i] = fmaxf(acc, 0.f);
}

// ---------------- launch ----------------------------------------------------
extern "C" void kernel_launch(void* const* d_in, const int* in_sizes, int n_in,
                              void* d_out, int out_size){
  (void)in_sizes; (void)n_in; (void)out_size;
  const float* feats=(const float*)d_in[0];
  const int*   bidx =(const int*)d_in[1];
  const int*   nbr  =(const int*)d_in[2];
  const float* W1 =(const float*)d_in[3];
  const float* g1 =(const float*)d_in[4];
  const float* b1 =(const float*)d_in[5];
  const float* W2 =(const float*)d_in[6];
  const float* g2 =(const float*)d_in[7];
  const float* b2 =(const float*)d_in[8];
  const float* Wk =(const float*)d_in[9];
  const float* gk =(const float*)d_in[10];
  const float* bk =(const float*)d_in[11];
  const float* fc1w=(const float*)d_in[12];
  const float* fc1b=(const float*)d_in[13];
  const float* fc2w=(const float*)d_in[14];
  const float* fc2b=(const float*)d_in[15];
  const float* ksw =(const float*)d_in[16];
  float* out=(float*)d_out;

  float *pConv,*pk0,*pk1,*pk2;
  __half2 *pHiA,*pHiB;
  uint32_t* pW;
  cudaGetSymbolAddress((void**)&pConv, g_conv);
  cudaGetSymbolAddress((void**)&pk0, g_kx0);
  cudaGetSymbolAddress((void**)&pk1, g_kx1);
  cudaGetSymbolAddress((void**)&pk2, g_kx2);
  cudaGetSymbolAddress((void**)&pHiA, g_hiA);
  cudaGetSymbolAddress((void**)&pHiB, g_hiB);
  cudaGetSymbolAddress((void**)&pW,  g_wswz);

  cudaFuncSetAttribute(conv_mma, cudaFuncAttributeMaxDynamicSharedMemorySize, SM_DYN);

  clear_all_kernel<<<2,256>>>();
  wprep_kernel<<<(5*KN*2048 + 255)/256, 256>>>(W1, W2, Wk);
  cvt_kernel<<<NPTS*CH/4/256, 256>>>((const float4*)feats, pHiA);

  struct Step {
    const __half *hi; const uint32_t* bw;
    const float *g, *b; int relu;
    float* fout; __half2 *ho;
  };
  Step steps[5] = {
    {(const __half*)pHiA, pW + 0*KN*2048, g1,      b1,      1, nullptr, pHiB},
    {(const __half*)pHiB, pW + 1*KN*2048, g2,      b2,      0, nullptr, pHiA},
    {(const __half*)pHiA, pW + 2*KN*2048, gk,      bk,      1, pk0,     pHiB},
    {(const __half*)pHiB, pW + 3*KN*2048, gk+CH,   bk+CH,   1, pk1,     pHiA},
    {(const __half*)pHiA, pW + 4*KN*2048, gk+2*CH, bk+2*CH, 1, pk2,     nullptr},
  };
  for (int s=0;s<5;s++){
    conv_mma<<<GRIDC, 256, SM_DYN>>>(steps[s].hi, nbr, steps[s].bw, pConv, s);
    bn2_kernel<<<NPTS*CH/4/256, 256>>>(pConv, steps[s].g, steps[s].b, steps[s].relu, s,
                                       steps[s].fout, steps[s].ho);
  }
  seg_kernel<<<400, CAQ>>>(bidx);
  fc_kernel<<<1,256>>>(bidx, fc1w, fc1b, fc2w, fc2b, ksw);
  final_kernel<<<(NPTS*CH)/256, 256>>>(feats, bidx, out);
}

// round 15
// speedup vs baseline: 1.1755x; 1.0354x over previous
#include <cuda_runtime.h>
#include <cuda_fp16.h>
#include <math.h>
#include <float.h>
#include <stdint.h>

#define NPTS 80000
#define CH   64
#define KN   27
#define NB   2
#define NXX  3
#define CAQ  192
#define HID  12
#define NTILES 625
#define GRIDC  592

// ---------------- scratch (device globals; no allocation allowed) ----------
__device__ __half g_conv[NPTS*CH];
__device__ __half g_kx0[NPTS*CH];
__device__ __half g_kx1[NPTS*CH];
__device__ __half g_kx2[NPTS*CH];
__device__ __half2 g_hiA[NPTS*CH/2];
__device__ __half2 g_hiB[NPTS*CH/2];
__device__ uint32_t g_wswz[5*KN*2048];      // W_hi fp16, mma-fragment packed (8KB/tap)
__device__ float g_sum[5*CH], g_sumsq[5*CH];
__device__ float g_segsum[NB*CAQ], g_segmax[NB*CAQ], g_att[NB*CAQ], g_wsig[NXX];

// ---------------- helpers ----------------------------------------------------
__device__ __forceinline__ uint32_t smem_u32(const void* p){
  uint32_t a;
  asm("{ .reg .u64 t; cvta.to.shared.u64 t, %1; cvt.u32.u64 %0, t; }" : "=r"(a) : "l"(p));
  return a;
}
__device__ __forceinline__ void ldsm_x4(uint32_t addr, uint32_t* r){
  asm volatile("ldmatrix.sync.aligned.m8n8.x4.shared.b16 {%0,%1,%2,%3}, [%4];"
    : "=r"(r[0]),"=r"(r[1]),"=r"(r[2]),"=r"(r[3]) : "r"(addr));
}
__device__ __forceinline__ void hmma(float* c, const uint32_t* a, uint32_t b0, uint32_t b1){
  asm volatile(
    "mma.sync.aligned.m16n8k16.row.col.f32.f16.f16.f32 "
    "{%0,%1,%2,%3}, {%4,%5,%6,%7}, {%8,%9}, {%0,%1,%2,%3};"
    : "+f"(c[0]), "+f"(c[1]), "+f"(c[2]), "+f"(c[3])
    : "r"(a[0]), "r"(a[1]), "r"(a[2]), "r"(a[3]), "r"(b0), "r"(b1));
}
__device__ __forceinline__ void cp16z(uint32_t sdst, const void* gsrc, int srcsz){
  asm volatile("cp.async.cg.shared.global [%0], [%1], 16, %2;" :: "r"(sdst), "l"(gsrc), "r"(srcsz));
}
#define CP_COMMIT() asm volatile("cp.async.commit_group;" ::: "memory")
#define CP_WAIT2()  asm volatile("cp.async.wait_group 2;" ::: "memory")
#define PAIR_BAR(id) asm volatile("bar.sync %0, 64;" :: "r"(id) : "memory")

__device__ __forceinline__ void atomicMaxFloat(float* addr, float val){
  int* ai = (int*)addr;
  int old = *ai;
  while (true){
    float fo = __int_as_float(old);
    if (fo >= val) break;
    int assumed = old;
    old = atomicCAS(ai, assumed, __float_as_int(val));
    if (old == assumed) break;
  }
}

// ---------------- weight prep: smem-staged, coalesced both sides ------------
// One block per (layer, tap): load 64x64 fp32 tile coalesced, emit fragment-
// packed fp16 (slot layout identical to previous rounds).
__global__ void wprep_kernel(const float* __restrict__ W1,
                             const float* __restrict__ W2,
                             const float* __restrict__ Wk){
  __shared__ float wt[4096];
  int tk = blockIdx.x;          // 0 .. 5*KN-1
  int l = tk/KN, k = tk - l*KN;
  const float* Ws = ((l==0)? W1 : (l==1)? W2 : (Wk + (size_t)(l-2)*KN*CH*CH)) + (size_t)k*CH*CH;
  int t = threadIdx.x;
  for (int i = t; i < 4096; i += 256) wt[i] = Ws[i];
  __syncthreads();
  for (int slot = t; slot < 2048; slot += 256){
    int r    = slot & 3;
    int L    = (slot >> 2) & 31;
    int rest = slot >> 7;
    int quad = rest & 1;
    int q    = (rest >> 1) & 3;
    int wn   = rest >> 3;
    int n  = wn*32 + quad*16 + (r>>1)*8 + (L>>2);
    int kk = q*16 + (L&3)*2 + (r&1)*8;
    __half b0 = __float2half(wt[kk*CH + n]);
    __half b1 = __float2half(wt[(kk+1)*CH + n]);
    g_wswz[tk*2048 + slot] =
        (uint32_t)__half_as_ushort(b0) | ((uint32_t)__half_as_ushort(b1) << 16);
  }
}

// ---------------- fp32 -> fp16 conversion of layer-0 input ------------------
__global__ void cvt_kernel(const float4* __restrict__ x,
                           __half2* __restrict__ ho){
  int i4 = blockIdx.x*256 + threadIdx.x;
  float4 v = x[i4];
  ho[2*i4]   = __halves2half2(__float2half(v.x), __float2half(v.y));
  ho[2*i4+1] = __halves2half2(__float2half(v.z), __float2half(v.w));
}

// ---------------- one-shot clears -------------------------------------------
__global__ void clear_all_kernel(){
  int t = blockIdx.x*256 + threadIdx.x;
  if (t < 5*CH){ g_sum[t]=0.f; g_sumsq[t]=0.f; }
  if (t < NB*CAQ){ g_segsum[t]=0.f; g_segmax[t]=-FLT_MAX; }
}

// ---------------- HMMA gathered conv (R14 body, fp16 output) ----------------
#define NBR_OFF 65536
#define SM_DYN (65536 + 13824 + 1024)

__device__ __forceinline__ void ldgB(const uint4* __restrict__ bw,
                                     int k, int q, int wn, int L, uint32_t* B){
  const uint4* p = bw + (size_t)k*512 + (size_t)((wn*4 + q)*2)*32 + L;
  uint4 v0 = __ldg(p);
  uint4 v1 = __ldg(p + 32);
  B[0]=v0.x; B[1]=v0.y; B[2]=v0.z; B[3]=v0.w;
  B[4]=v1.x; B[5]=v1.y; B[6]=v1.z; B[7]=v1.w;
}

__device__ __forceinline__ void fillA(
    int k, int buf, int t, uint32_t sb, const int* __restrict__ snbr,
    const __half* __restrict__ hi)
{
  int r = (t>>6)*32 + ((t&63)>>1);
  int half = t & 1;
  int idx = snbr[r*KN + k];
  int sz = idx>=0 ? 16 : 0;
  int sidx = idx>=0 ? idx : 0;
  const char* asrc = (const char*)(hi + (size_t)sidx*CH);
  uint32_t rbase = sb + (uint32_t)buf*16384 + (uint32_t)r*128;
  int xr = r & 7;
#pragma unroll
  for (int j=0;j<4;j++){
    int c = half*4 + j;
    int sw = c ^ xr;
    cp16z(rbase + sw*16, asrc + c*16, sz);
  }
}

__global__ void __launch_bounds__(256,2) conv_mma(
    const __half* __restrict__ hi,
    const int* __restrict__ nbr, const uint32_t* __restrict__ bswz,
    __half* __restrict__ dst, int layer)
{
  extern __shared__ char smraw[];
  char* sm = (char*)(((uintptr_t)smraw + 1023) & ~(uintptr_t)1023);
  const uint32_t sb = smem_u32(sm);
  int* snbr = (int*)(sm + NBR_OFF);
  __shared__ float sred[128];
  const uint4* bw = (const uint4*)bswz;

  const int t   = threadIdx.x;
  const int L   = t & 31;
  const int wid = t >> 5;
  const int wm  = wid >> 1;
  const int wn  = wid & 1;
  const int barid = 1 + wm;

  const int arow_l  = ((L>>3)&1)*8 + (L&7);
  const int a_clane = (L>>4);
  const int arow    = wm*32 + arow_l;
  const int axor    = arow & 7;

  for (int tile = blockIdx.x; tile < NTILES; tile += GRIDC){
    const int row0 = tile * 128;

    if (t < 128) sred[t] = 0.f;

    {
      const int* src = nbr + (size_t)row0*KN;
#pragma unroll
      for (int i = 0; i < 14; i++){
        int o = t + i*256;
        if (o < 128*KN) snbr[o] = src[o];
      }
    }
    __syncthreads();

    float acc[2][4][4];
#pragma unroll
    for (int s=0;s<2;s++)
#pragma unroll
      for (int nb=0;nb<4;nb++)
#pragma unroll
        for (int i=0;i<4;i++) acc[s][nb][i]=0.f;

    fillA(0, 0, t, sb, snbr, hi); CP_COMMIT();
    fillA(1, 1, t, sb, snbr, hi); CP_COMMIT();
    fillA(2, 2, t, sb, snbr, hi); CP_COMMIT();

    uint32_t Bb0[8], Bb1[8];
    ldgB(bw, 0, 0, wn, L, Bb0);

    for (int k = 0; k < KN; k++){
      CP_WAIT2();
      PAIR_BAR(barid);

      if (k+3 < KN) fillA(k+3, (k+3)&3, t, sb, snbr, hi);
      CP_COMMIT();

      const uint32_t Arow = sb + (uint32_t)(k&3)*16384 + (uint32_t)arow*128;

#pragma unroll
      for (int q=0; q<4; q++){
        uint32_t* Bcur = (q&1) ? Bb1 : Bb0;
        uint32_t* Bnxt = (q&1) ? Bb0 : Bb1;
        if (q < 3) ldgB(bw, k, q+1, wn, L, Bnxt);
        else       ldgB(bw, (k+1<KN)?(k+1):k, 0, wn, L, Bnxt);

        uint32_t Ah0[4], Ah1[4];
        uint32_t ah = Arow + (uint32_t)(((q*2 + a_clane) ^ axor)*16);
        ldsm_x4(ah, Ah0);
        ldsm_x4(ah + 16*128, Ah1);

        hmma(acc[0][0], Ah0, Bcur[0], Bcur[1]);
        hmma(acc[0][1], Ah0, Bcur[2], Bcur[3]);
        hmma(acc[0][2], Ah0, Bcur[4], Bcur[5]);
        hmma(acc[0][3], Ah0, Bcur[6], Bcur[7]);
        hmma(acc[1][0], Ah1, Bcur[0], Bcur[1]);
        hmma(acc[1][1], Ah1, Bcur[2], Bcur[3]);
        hmma(acc[1][2], Ah1, Bcur[4], Bcur[5]);
        hmma(acc[1][3], Ah1, Bcur[6], Bcur[7]);
      }
    }

    // ---- epilogue: fp16 stores + fused per-channel stats (fp32 accs)
#pragma unroll
    for (int s=0;s<2;s++){
      int r = row0 + wm*32 + s*16 + (L>>2);
#pragma unroll
      for (int nb=0;nb<4;nb++){
        int col = wn*32 + nb*8 + (L&3)*2;
        float* c = acc[s][nb];
        *(__half2*)&dst[(size_t)r*CH + col]     = __floats2half2_rn(c[0], c[1]);
        *(__half2*)&dst[(size_t)(r+8)*CH + col] = __floats2half2_rn(c[2], c[3]);
      }
    }
#pragma unroll
    for (int nb=0;nb<4;nb++){
      float sc0=0.f, sc1=0.f, qc0=0.f, qc1=0.f;
#pragma unroll
      for (int s=0;s<2;s++){
        float* c = acc[s][nb];
        sc0 += c[0]+c[2]; qc0 += c[0]*c[0]+c[2]*c[2];
        sc1 += c[1]+c[3]; qc1 += c[1]*c[1]+c[3]*c[3];
      }
#pragma unroll
      for (int m=4;m<32;m<<=1){
        sc0 += __shfl_xor_sync(0xFFFFFFFFu, sc0, m);
        sc1 += __shfl_xor_sync(0xFFFFFFFFu, sc1, m);
        qc0 += __shfl_xor_sync(0xFFFFFFFFu, qc0, m);
        qc1 += __shfl_xor_sync(0xFFFFFFFFu, qc1, m);
      }
      if (L < 4){
        int col = wn*32 + nb*8 + L*2;
        atomicAdd(&sred[col],    sc0); atomicAdd(&sred[col+1],    sc1);
        atomicAdd(&sred[64+col], qc0); atomicAdd(&sred[64+col+1], qc1);
      }
    }
    __syncthreads();
    if (t < 64){
      atomicAdd(&g_sum[layer*CH + t],   sred[t]);
      atomicAdd(&g_sumsq[layer*CH + t], sred[64+t]);
    }
    __syncthreads();
  }
}

// ---------------- BN apply (fp16 in) + emit fp16 kx and/or fp16 next-input --
__global__ void bn2_kernel(const __half* __restrict__ x, const float* __restrict__ gg,
                           const float* __restrict__ bb, int relu, int layer,
                           __half* __restrict__ fout,
                           __half2* __restrict__ ho){
  __shared__ float sc[64], bi[64];
  int t = threadIdx.x;
  if (t < 64){
    float m = g_sum[layer*CH + t]*(1.f/NPTS);
    float v = g_sumsq[layer*CH + t]*(1.f/NPTS) - m*m;
    float s = rsqrtf(v + 1e-5f) * gg[t];
    sc[t] = s; bi[t] = bb[t] - m*s;
  }
  __syncthreads();
  int i4 = blockIdx.x*256 + t;          // group of 4 halves
  uint2 hv = ((const uint2*)x)[i4];
  float2 f01 = __half22float2(*(__half2*)&hv.x);
  float2 f23 = __half22float2(*(__half2*)&hv.y);
  int c = (i4 & 15)*4;
  float v0 = f01.x*sc[c]  +bi[c];
  float v1 = f01.y*sc[c+1]+bi[c+1];
  float v2 = f23.x*sc[c+2]+bi[c+2];
  float v3 = f23.y*sc[c+3]+bi[c+3];
  if (relu){ v0=fmaxf(v0,0.f); v1=fmaxf(v1,0.f); v2=fmaxf(v2,0.f); v3=fmaxf(v3,0.f); }
  __half2 h01 = __floats2half2_rn(v0, v1);
  __half2 h23 = __floats2half2_rn(v2, v3);
  if (fout){
    __half2* fp = (__half2*)fout;
    fp[2*i4]   = h01;
    fp[2*i4+1] = h23;
  }
  if (ho){
    ho[2*i4]   = h01;
    ho[2*i4+1] = h23;
  }
}

// ---------------- segment sum/max over batches (B=2), 192 channels ---------
__global__ void seg_kernel(const int* __restrict__ bidx){
  int j = threadIdx.x;
  const __half* kxp = (j<64)? g_kx0 : ((j<128)? g_kx1 : g_kx2);
  int c = j & 63;
  int n0 = blockIdx.x*200, n1 = n0+200;
  float s0=0.f, s1=0.f, m0=-FLT_MAX, m1=-FLT_MAX;
  for (int n=n0;n<n1;n++){
    float v = __half2float(kxp[n*CH + c]);
    if (bidx[n]==0){ s0+=v; m0=fmaxf(m0,v); } else { s1+=v; m1=fmaxf(m1,v); }
  }
  atomicAdd(&g_segsum[j], s0);
  atomicAdd(&g_segsum[CAQ+j], s1);
  atomicMaxFloat(&g_segmax[j], m0);
  atomicMaxFloat(&g_segmax[CAQ+j], m1);
}

// ---------------- tiny FC + sigmoid attention ------------------------------
__global__ void fc_kernel(const int* __restrict__ bidx,
    const float* __restrict__ w1, const float* __restrict__ b1,
    const float* __restrict__ w2, const float* __restrict__ b2,
    const float* __restrict__ ksw)
{
  __shared__ float ha[NB][HID], hm[NB][HID];
  __shared__ int red[256];
  __shared__ int scnt[NB];
  int t = threadIdx.x;
  int c0 = 0;
  for (int n=t; n<NPTS; n+=256) c0 += (bidx[n]==0);
  red[t]=c0; __syncthreads();
  for (int s=128;s>0;s>>=1){ if (t<s) red[t]+=red[t+s]; __syncthreads(); }
  if (t==0){ scnt[0]=red[0]; scnt[1]=NPTS-red[0]; }
  __syncthreads();
  if (t<48){
    int which = t/24;
    int b  = (t/12)%2;
    int tt = t%12;
    float s = b1[tt];
    float inv = 1.f/(float)scnt[b];
    for (int j=0;j<CAQ;j++){
      float z = which ? g_segmax[b*CAQ+j] : g_segsum[b*CAQ+j]*inv;
      s += z * w1[j*HID+tt];
    }
    s = fmaxf(s,0.f);
    if (which) hm[b][tt]=s; else ha[b][tt]=s;
  }
  __syncthreads();
  for (int o=t; o<NB*CAQ; o+=256){
    int b=o/CAQ, j=o%CAQ;
    float sa=b2[j], sm=b2[j];
    for (int tt=0;tt<HID;tt++){ sa += ha[b][tt]*w2[tt*CAQ+j]; sm += hm[b][tt]*w2[tt*CAQ+j]; }
    float s = sa+sm;
    g_att[o] = 1.f/(1.f+expf(-s));
  }
  if (t<NXX) g_wsig[t] = 1.f/(1.f+expf(-ksw[t]));
}

// ---------------- fusion epilogue ------------------------------------------
__device__ __forceinline__ float kx_read(int sel, int off){
  __half h = sel==0 ? g_kx0[off] : (sel==1 ? g_kx1[off] : g_kx2[off]);
  return __half2float(h);
}
__global__ void final_kernel(const float* __restrict__ feats,
                             const int* __restrict__ bidx,
                             float* __restrict__ out){
  int i = blockIdx.x*256 + threadIdx.x;
  int n = i >> 6, c = i & 63;
  int b = bidx[n];
  float acc = feats[i];
#pragma unroll
  for (int ii=0; ii<NXX; ii++){
    int j = 3*c + ii;
    int sel = j >> 6, col = j & 63;
    float xj  = kx_read(sel, n*CH + col);
    float kxi = kx_read(ii, i);
    acc += g_wsig[ii] * (kxi + xj * g_att[b*CAQ + j]);
  }
  out[i] = fmaxf(acc, 0.f);
}

// ---------------- launch ----------------------------------------------------
extern "C" void kernel_launch(void* const* d_in, const int* in_sizes, int n_in,
                              void* d_out, int out_size){
  (void)in_sizes; (void)n_in; (void)out_size;
  const float* feats=(const float*)d_in[0];
  const int*   bidx =(const int*)d_in[1];
  const int*   nbr  =(const int*)d_in[2];
  const float* W1 =(const float*)d_in[3];
  const float* g1 =(const float*)d_in[4];
  const float* b1 =(const float*)d_in[5];
  const float* W2 =(const float*)d_in[6];
  const float* g2 =(const float*)d_in[7];
  const float* b2 =(const float*)d_in[8];
  const float* Wk =(const float*)d_in[9];
  const float* gk =(const float*)d_in[10];
  const float* bk =(const float*)d_in[11];
  const float* fc1w=(const float*)d_in[12];
  const float* fc1b=(const float*)d_in[13];
  const float* fc2w=(const float*)d_in[14];
  const float* fc2b=(const float*)d_in[15];
  const float* ksw =(const float*)d_in[16];
  float* out=(float*)d_out;

  __half *pConv,*pk0,*pk1,*pk2;
  __half2 *pHiA,*pHiB;
  uint32_t* pW;
  cudaGetSymbolAddress((void**)&pConv, g_conv);
  cudaGetSymbolAddress((void**)&pk0, g_kx0);
  cudaGetSymbolAddress((void**)&pk1, g_kx1);
  cudaGetSymbolAddress((void**)&pk2, g_kx2);
  cudaGetSymbolAddress((void**)&pHiA, g_hiA);
  cudaGetSymbolAddress((void**)&pHiB, g_hiB);
  cudaGetSymbolAddress((void**)&pW,  g_wswz);

  cudaFuncSetAttribute(conv_mma, cudaFuncAttributeMaxDynamicSharedMemorySize, SM_DYN);

  clear_all_kernel<<<2,256>>>();
  wprep_kernel<<<5*KN, 256>>>(W1, W2, Wk);
  cvt_kernel<<<NPTS*CH/4/256, 256>>>((const float4*)feats, pHiA);

  struct Step {
    const __half *hi; const uint32_t* bw;
    const float *g, *b; int relu;
    __half* fout; __half2 *ho;
  };
  Step steps[5] = {
    {(const __half*)pHiA, pW + 0*KN*2048, g1,      b1,      1, nullptr, pHiB},
    {(const __half*)pHiB, pW + 1*KN*2048, g2,      b2,      0, nullptr, pHiA},
    {(const __half*)pHiA, pW + 2*KN*2048, gk,      bk,      1, pk0,     pHiB},
    {(const __half*)pHiB, pW + 3*KN*2048, gk+CH,   bk+CH,   1, pk1,     pHiA},
    {(const __half*)pHiA, pW + 4*KN*2048, gk+2*CH, bk+2*CH, 1, pk2,     nullptr},
  };
  for (int s=0;s<5;s++){
    conv_mma<<<GRIDC, 256, SM_DYN>>>(steps[s].hi, nbr, steps[s].bw, pConv, s);
    bn2_kernel<<<NPTS*CH/4/256, 256>>>(pConv, steps[s].g, steps[s].b, steps[s].relu, s,
                                       steps[s].fout, steps[s].ho);
  }
  seg_kernel<<<400, CAQ>>>(bidx);
  fc_kernel<<<1,256>>>(bidx, fc1w, fc1b, fc2w, fc2b, ksw);
  final_kernel<<<(NPTS*CH)/256, 256>>>(feats, bidx, out);
}

// round 16
// speedup vs baseline: 1.1865x; 1.0094x over previous
#include <cuda_runtime.h>
#include <cuda_fp16.h>
#include <math.h>
#include <float.h>
#include <stdint.h>

#define NPTS 80000
#define CH   64
#define KN   27
#define NB   2
#define NXX  3
#define CAQ  192
#define HID  12
#define NTILES 625
#define GRIDC  592

// ---------------- scratch (device globals; no allocation allowed) ----------
__device__ __half g_conv[NPTS*CH];
__device__ __half g_kx0[NPTS*CH];
__device__ __half g_kx1[NPTS*CH];
__device__ __half g_kx2[NPTS*CH];
__device__ __half2 g_hiA[NPTS*CH/2];
__device__ __half2 g_hiB[NPTS*CH/2];
__device__ uint32_t g_wswz[5*KN*2048];      // W_hi fp16, mma-fragment packed (8KB/tap)
__device__ float g_sum[5*CH], g_sumsq[5*CH];
__device__ float g_segsum[NB*CAQ], g_segmax[NB*CAQ], g_att[NB*CAQ], g_wsig[NXX];
__device__ int g_cnt0;

// ---------------- helpers ----------------------------------------------------
__device__ __forceinline__ uint32_t smem_u32(const void* p){
  uint32_t a;
  asm("{ .reg .u64 t; cvta.to.shared.u64 t, %1; cvt.u32.u64 %0, t; }" : "=r"(a) : "l"(p));
  return a;
}
__device__ __forceinline__ void ldsm_x4(uint32_t addr, uint32_t* r){
  asm volatile("ldmatrix.sync.aligned.m8n8.x4.shared.b16 {%0,%1,%2,%3}, [%4];"
    : "=r"(r[0]),"=r"(r[1]),"=r"(r[2]),"=r"(r[3]) : "r"(addr));
}
__device__ __forceinline__ void hmma(float* c, const uint32_t* a, uint32_t b0, uint32_t b1){
  asm volatile(
    "mma.sync.aligned.m16n8k16.row.col.f32.f16.f16.f32 "
    "{%0,%1,%2,%3}, {%4,%5,%6,%7}, {%8,%9}, {%0,%1,%2,%3};"
    : "+f"(c[0]), "+f"(c[1]), "+f"(c[2]), "+f"(c[3])
    : "r"(a[0]), "r"(a[1]), "r"(a[2]), "r"(a[3]), "r"(b0), "r"(b1));
}
__device__ __forceinline__ void cp16z(uint32_t sdst, const void* gsrc, int srcsz){
  asm volatile("cp.async.cg.shared.global [%0], [%1], 16, %2;" :: "r"(sdst), "l"(gsrc), "r"(srcsz));
}
#define CP_COMMIT() asm volatile("cp.async.commit_group;" ::: "memory")
#define CP_WAIT2()  asm volatile("cp.async.wait_group 2;" ::: "memory")
#define PAIR_BAR(id) asm volatile("bar.sync %0, 64;" :: "r"(id) : "memory")

__device__ __forceinline__ void atomicMaxFloat(float* addr, float val){
  int* ai = (int*)addr;
  int old = *ai;
  while (true){
    float fo = __int_as_float(old);
    if (fo >= val) break;
    int assumed = old;
    old = atomicCAS(ai, assumed, __float_as_int(val));
    if (old == assumed) break;
  }
}

// ---------------- weight prep: smem-staged, coalesced both sides ------------
__global__ void wprep_kernel(const float* __restrict__ W1,
                             const float* __restrict__ W2,
                             const float* __restrict__ Wk){
  __shared__ float wt[4096];
  int tk = blockIdx.x;          // 0 .. 5*KN-1
  int l = tk/KN, k = tk - l*KN;
  const float* Ws = ((l==0)? W1 : (l==1)? W2 : (Wk + (size_t)(l-2)*KN*CH*CH)) + (size_t)k*CH*CH;
  int t = threadIdx.x;
  for (int i = t; i < 4096; i += 256) wt[i] = Ws[i];
  __syncthreads();
  for (int slot = t; slot < 2048; slot += 256){
    int r    = slot & 3;
    int L    = (slot >> 2) & 31;
    int rest = slot >> 7;
    int quad = rest & 1;
    int q    = (rest >> 1) & 3;
    int wn   = rest >> 3;
    int n  = wn*32 + quad*16 + (r>>1)*8 + (L>>2);
    int kk = q*16 + (L&3)*2 + (r&1)*8;
    __half b0 = __float2half(wt[kk*CH + n]);
    __half b1 = __float2half(wt[(kk+1)*CH + n]);
    g_wswz[tk*2048 + slot] =
        (uint32_t)__half_as_ushort(b0) | ((uint32_t)__half_as_ushort(b1) << 16);
  }
}

// ---------------- fp32 -> fp16 conversion of layer-0 input ------------------
__global__ void cvt_kernel(const float4* __restrict__ x,
                           __half2* __restrict__ ho){
  int i4 = blockIdx.x*256 + threadIdx.x;
  float4 v = x[i4];
  ho[2*i4]   = __halves2half2(__float2half(v.x), __float2half(v.y));
  ho[2*i4+1] = __halves2half2(__float2half(v.z), __float2half(v.w));
}

// ---------------- one-shot clears -------------------------------------------
__global__ void clear_all_kernel(){
  int t = blockIdx.x*256 + threadIdx.x;
  if (t < 5*CH){ g_sum[t]=0.f; g_sumsq[t]=0.f; }
  if (t < NB*CAQ){ g_segsum[t]=0.f; g_segmax[t]=-FLT_MAX; }
  if (t == 5*CH) g_cnt0 = 0;
}

// ---------------- HMMA gathered conv (R15 body, unchanged) ------------------
#define NBR_OFF 65536
#define SM_DYN (65536 + 13824 + 1024)

__device__ __forceinline__ void ldgB(const uint4* __restrict__ bw,
                                     int k, int q, int wn, int L, uint32_t* B){
  const uint4* p = bw + (size_t)k*512 + (size_t)((wn*4 + q)*2)*32 + L;
  uint4 v0 = __ldg(p);
  uint4 v1 = __ldg(p + 32);
  B[0]=v0.x; B[1]=v0.y; B[2]=v0.z; B[3]=v0.w;
  B[4]=v1.x; B[5]=v1.y; B[6]=v1.z; B[7]=v1.w;
}

__device__ __forceinline__ void fillA(
    int k, int buf, int t, uint32_t sb, const int* __restrict__ snbr,
    const __half* __restrict__ hi)
{
  int r = (t>>6)*32 + ((t&63)>>1);
  int half = t & 1;
  int idx = snbr[r*KN + k];
  int sz = idx>=0 ? 16 : 0;
  int sidx = idx>=0 ? idx : 0;
  const char* asrc = (const char*)(hi + (size_t)sidx*CH);
  uint32_t rbase = sb + (uint32_t)buf*16384 + (uint32_t)r*128;
  int xr = r & 7;
#pragma unroll
  for (int j=0;j<4;j++){
    int c = half*4 + j;
    int sw = c ^ xr;
    cp16z(rbase + sw*16, asrc + c*16, sz);
  }
}

__global__ void __launch_bounds__(256,2) conv_mma(
    const __half* __restrict__ hi,
    const int* __restrict__ nbr, const uint32_t* __restrict__ bswz,
    __half* __restrict__ dst, int layer)
{
  extern __shared__ char smraw[];
  char* sm = (char*)(((uintptr_t)smraw + 1023) & ~(uintptr_t)1023);
  const uint32_t sb = smem_u32(sm);
  int* snbr = (int*)(sm + NBR_OFF);
  __shared__ float sred[128];
  const uint4* bw = (const uint4*)bswz;

  const int t   = threadIdx.x;
  const int L   = t & 31;
  const int wid = t >> 5;
  const int wm  = wid >> 1;
  const int wn  = wid & 1;
  const int barid = 1 + wm;

  const int arow_l  = ((L>>3)&1)*8 + (L&7);
  const int a_clane = (L>>4);
  const int arow    = wm*32 + arow_l;
  const int axor    = arow & 7;

  for (int tile = blockIdx.x; tile < NTILES; tile += GRIDC){
    const int row0 = tile * 128;

    if (t < 128) sred[t] = 0.f;

    {
      const int* src = nbr + (size_t)row0*KN;
#pragma unroll
      for (int i = 0; i < 14; i++){
        int o = t + i*256;
        if (o < 128*KN) snbr[o] = src[o];
      }
    }
    __syncthreads();

    float acc[2][4][4];
#pragma unroll
    for (int s=0;s<2;s++)
#pragma unroll
      for (int nb=0;nb<4;nb++)
#pragma unroll
        for (int i=0;i<4;i++) acc[s][nb][i]=0.f;

    fillA(0, 0, t, sb, snbr, hi); CP_COMMIT();
    fillA(1, 1, t, sb, snbr, hi); CP_COMMIT();
    fillA(2, 2, t, sb, snbr, hi); CP_COMMIT();

    uint32_t Bb0[8], Bb1[8];
    ldgB(bw, 0, 0, wn, L, Bb0);

    for (int k = 0; k < KN; k++){
      CP_WAIT2();
      PAIR_BAR(barid);

      if (k+3 < KN) fillA(k+3, (k+3)&3, t, sb, snbr, hi);
      CP_COMMIT();

      const uint32_t Arow = sb + (uint32_t)(k&3)*16384 + (uint32_t)arow*128;

#pragma unroll
      for (int q=0; q<4; q++){
        uint32_t* Bcur = (q&1) ? Bb1 : Bb0;
        uint32_t* Bnxt = (q&1) ? Bb0 : Bb1;
        if (q < 3) ldgB(bw, k, q+1, wn, L, Bnxt);
        else       ldgB(bw, (k+1<KN)?(k+1):k, 0, wn, L, Bnxt);

        uint32_t Ah0[4], Ah1[4];
        uint32_t ah = Arow + (uint32_t)(((q*2 + a_clane) ^ axor)*16);
        ldsm_x4(ah, Ah0);
        ldsm_x4(ah + 16*128, Ah1);

        hmma(acc[0][0], Ah0, Bcur[0], Bcur[1]);
        hmma(acc[0][1], Ah0, Bcur[2], Bcur[3]);
        hmma(acc[0][2], Ah0, Bcur[4], Bcur[5]);
        hmma(acc[0][3], Ah0, Bcur[6], Bcur[7]);
        hmma(acc[1][0], Ah1, Bcur[0], Bcur[1]);
        hmma(acc[1][1], Ah1, Bcur[2], Bcur[3]);
        hmma(acc[1][2], Ah1, Bcur[4], Bcur[5]);
        hmma(acc[1][3], Ah1, Bcur[6], Bcur[7]);
      }
    }

    // ---- epilogue: fp16 stores + fused per-channel stats (fp32 accs)
#pragma unroll
    for (int s=0;s<2;s++){
      int r = row0 + wm*32 + s*16 + (L>>2);
#pragma unroll
      for (int nb=0;nb<4;nb++){
        int col = wn*32 + nb*8 + (L&3)*2;
        float* c = acc[s][nb];
        *(__half2*)&dst[(size_t)r*CH + col]     = __floats2half2_rn(c[0], c[1]);
        *(__half2*)&dst[(size_t)(r+8)*CH + col] = __floats2half2_rn(c[2], c[3]);
      }
    }
#pragma unroll
    for (int nb=0;nb<4;nb++){
      float sc0=0.f, sc1=0.f, qc0=0.f, qc1=0.f;
#pragma unroll
      for (int s=0;s<2;s++){
        float* c = acc[s][nb];
        sc0 += c[0]+c[2]; qc0 += c[0]*c[0]+c[2]*c[2];
        sc1 += c[1]+c[3]; qc1 += c[1]*c[1]+c[3]*c[3];
      }
#pragma unroll
      for (int m=4;m<32;m<<=1){
        sc0 += __shfl_xor_sync(0xFFFFFFFFu, sc0, m);
        sc1 += __shfl_xor_sync(0xFFFFFFFFu, sc1, m);
        qc0 += __shfl_xor_sync(0xFFFFFFFFu, qc0, m);
        qc1 += __shfl_xor_sync(0xFFFFFFFFu, qc1, m);
      }
      if (L < 4){
        int col = wn*32 + nb*8 + L*2;
        atomicAdd(&sred[col],    sc0); atomicAdd(&sred[col+1],    sc1);
        atomicAdd(&sred[64+col], qc0); atomicAdd(&sred[64+col+1], qc1);
      }
    }
    __syncthreads();
    if (t < 64){
      atomicAdd(&g_sum[layer*CH + t],   sred[t]);
      atomicAdd(&g_sumsq[layer*CH + t], sred[64+t]);
    }
    __syncthreads();
  }
}

// ---------------- BN apply (fp16 in) -> single fp16 output ------------------
__global__ void bn2_kernel(const __half* __restrict__ x, const float* __restrict__ gg,
                           const float* __restrict__ bb, int relu, int layer,
                           __half2* __restrict__ outp){
  __shared__ float sc[64], bi[64];
  int t = threadIdx.x;
  if (t < 64){
    float m = g_sum[layer*CH + t]*(1.f/NPTS);
    float v = g_sumsq[layer*CH + t]*(1.f/NPTS) - m*m;
    float s = rsqrtf(v + 1e-5f) * gg[t];
    sc[t] = s; bi[t] = bb[t] - m*s;
  }
  __syncthreads();
  int i4 = blockIdx.x*256 + t;          // group of 4 halves
  uint2 hv = ((const uint2*)x)[i4];
  float2 f01 = __half22float2(*(__half2*)&hv.x);
  float2 f23 = __half22float2(*(__half2*)&hv.y);
  int c = (i4 & 15)*4;
  float v0 = f01.x*sc[c]  +bi[c];
  float v1 = f01.y*sc[c+1]+bi[c+1];
  float v2 = f23.x*sc[c+2]+bi[c+2];
  float v3 = f23.y*sc[c+3]+bi[c+3];
  if (relu){ v0=fmaxf(v0,0.f); v1=fmaxf(v1,0.f); v2=fmaxf(v2,0.f); v3=fmaxf(v3,0.f); }
  outp[2*i4]   = __floats2half2_rn(v0, v1);
  outp[2*i4+1] = __floats2half2_rn(v2, v3);
}

// ---------------- segment sum/max + batch count ------------------------------
__global__ void seg_kernel(const int* __restrict__ bidx){
  int j = threadIdx.x;
  const __half* kxp = (j<64)? g_kx0 : ((j<128)? g_kx1 : g_kx2);
  int c = j & 63;
  int n0 = blockIdx.x*200, n1 = n0+200;
  float s0=0.f, s1=0.f, m0=-FLT_MAX, m1=-FLT_MAX;
  int cnt0 = 0;
  for (int n=n0;n<n1;n++){
    int b = bidx[n];
    float v = __half2float(kxp[n*CH + c]);
    if (b==0){ s0+=v; m0=fmaxf(m0,v); cnt0++; } else { s1+=v; m1=fmaxf(m1,v); }
  }
  atomicAdd(&g_segsum[j], s0);
  atomicAdd(&g_segsum[CAQ+j], s1);
  atomicMaxFloat(&g_segmax[j], m0);
  atomicMaxFloat(&g_segmax[CAQ+j], m1);
  if (j == 0) atomicAdd(&g_cnt0, cnt0);
}

// ---------------- tiny FC + sigmoid attention ------------------------------
__global__ void fc_kernel(const float* __restrict__ w1, const float* __restrict__ b1,
                          const float* __restrict__ w2, const float* __restrict__ b2,
                          const float* __restrict__ ksw)
{
  __shared__ float ha[NB][HID], hm[NB][HID];
  int t = threadIdx.x;
  int cnt0 = g_cnt0;
  if (t<48){
    int which = t/24;
    int b  = (t/12)%2;
    int tt = t%12;
    float s = b1[tt];
    float inv = 1.f/(float)(b==0 ? cnt0 : NPTS-cnt0);
    for (int j=0;j<CAQ;j++){
      float z = which ? g_segmax[b*CAQ+j] : g_segsum[b*CAQ+j]*inv;
      s += z * w1[j*HID+tt];
    }
    s = fmaxf(s,0.f);
    if (which) hm[b][tt]=s; else ha[b][tt]=s;
  }
  __syncthreads();
  for (int o=t; o<NB*CAQ; o+=256){
    int b=o/CAQ, j=o%CAQ;
    float sa=b2[j], sm=b2[j];
    for (int tt=0;tt<HID;tt++){ sa += ha[b][tt]*w2[tt*CAQ+j]; sm += hm[b][tt]*w2[tt*CAQ+j]; }
    float s = sa+sm;
    g_att[o] = 1.f/(1.f+expf(-s));
  }
  if (t<NXX) g_wsig[t] = 1.f/(1.f+expf(-ksw[t]));
}

// ---------------- fusion epilogue ------------------------------------------
__device__ __forceinline__ float kx_read(int sel, int off){
  __half h = sel==0 ? g_kx0[off] : (sel==1 ? g_kx1[off] : g_kx2[off]);
  return __half2float(h);
}
__global__ void final_kernel(const float* __restrict__ feats,
                             const int* __restrict__ bidx,
                             float* __restrict__ out){
  int i = blockIdx.x*256 + threadIdx.x;
  int n = i >> 6, c = i & 63;
  int b = bidx[n];
  float acc = feats[i];
#pragma unroll
  for (int ii=0; ii<NXX; ii++){
    int j = 3*c + ii;
    int sel = j >> 6, col = j & 63;
    float xj  = kx_read(sel, n*CH + col);
    float kxi = kx_read(ii, i);
    acc += g_wsig[ii] * (kxi + xj * g_att[b*CAQ + j]);
  }
  out[i] = fmaxf(acc, 0.f);
}

// ---------------- launch ----------------------------------------------------
extern "C" void kernel_launch(void* const* d_in, const int* in_sizes, int n_in,
                              void* d_out, int out_size){
  (void)in_sizes; (void)n_in; (void)out_size;
  const float* feats=(const float*)d_in[0];
  const int*   bidx =(const int*)d_in[1];
  const int*   nbr  =(const int*)d_in[2];
  const float* W1 =(const float*)d_in[3];
  const float* g1 =(const float*)d_in[4];
  const float* b1 =(const float*)d_in[5];
  const float* W2 =(const float*)d_in[6];
  const float* g2 =(const float*)d_in[7];
  const float* b2 =(const float*)d_in[8];
  const float* Wk =(const float*)d_in[9];
  const float* gk =(const float*)d_in[10];
  const float* bk =(const float*)d_in[11];
  const float* fc1w=(const float*)d_in[12];
  const float* fc1b=(const float*)d_in[13];
  const float* fc2w=(const float*)d_in[14];
  const float* fc2b=(const float*)d_in[15];
  const float* ksw =(const float*)d_in[16];
  float* out=(float*)d_out;

  __half *pConv,*pk0,*pk1,*pk2;
  __half2 *pHiA,*pHiB;
  uint32_t* pW;
  cudaGetSymbolAddress((void**)&pConv, g_conv);
  cudaGetSymbolAddress((void**)&pk0, g_kx0);
  cudaGetSymbolAddress((void**)&pk1, g_kx1);
  cudaGetSymbolAddress((void**)&pk2, g_kx2);
  cudaGetSymbolAddress((void**)&pHiA, g_hiA);
  cudaGetSymbolAddress((void**)&pHiB, g_hiB);
  cudaGetSymbolAddress((void**)&pW,  g_wswz);

  cudaFuncSetAttribute(conv_mma, cudaFuncAttributeMaxDynamicSharedMemorySize, SM_DYN);

  clear_all_kernel<<<2,256>>>();
  wprep_kernel<<<5*KN, 256>>>(W1, W2, Wk);
  cvt_kernel<<<NPTS*CH/4/256, 256>>>((const float4*)feats, pHiA);

  // bn2 writes ONE array per layer; layers 2-4 feed the next conv from kx directly.
  struct Step {
    const __half *hi; const uint32_t* bw;
    const float *g, *b; int relu;
    __half2* outp;
  };
  Step steps[5] = {
    {(const __half*)pHiA, pW + 0*KN*2048, g1,      b1,      1, pHiB},
    {(const __half*)pHiB, pW + 1*KN*2048, g2,      b2,      0, pHiA},
    {(const __half*)pHiA, pW + 2*KN*2048, gk,      bk,      1, (__half2*)pk0},
    {(const __half*)pk0,  pW + 3*KN*2048, gk+CH,   bk+CH,   1, (__half2*)pk1},
    {(const __half*)pk1,  pW + 4*KN*2048, gk+2*CH, bk+2*CH, 1, (__half2*)pk2},
  };
  for (int s=0;s<5;s++){
    conv_mma<<<GRIDC, 256, SM_DYN>>>(steps[s].hi, nbr, steps[s].bw, pConv, s);
    bn2_kernel<<<NPTS*CH/4/256, 256>>>(pConv, steps[s].g, steps[s].b, steps[s].relu, s,
                                       steps[s].outp);
  }
  seg_kernel<<<400, CAQ>>>(bidx);
  fc_kernel<<<1,256>>>(fc1w, fc1b, fc2w, fc2b, ksw);
  final_kernel<<<(NPTS*CH)/256, 256>>>(feats, bidx, out);
}

// round 17
// speedup vs baseline: 1.2022x; 1.0133x over previous
#include <cuda_runtime.h>
#include <cuda_fp16.h>
#include <math.h>
#include <float.h>
#include <stdint.h>

#define NPTS 80000
#define CH   64
#define KN   27
#define NB   2
#define NXX  3
#define CAQ  192
#define HID  12
#define NTILES 625
#define GRIDC  592

// ---------------- scratch (device globals; no allocation allowed) ----------
__device__ __half g_conv[NPTS*CH];
__device__ __half g_kx0[NPTS*CH];
__device__ __half g_kx1[NPTS*CH];
__device__ __half2 g_hiA[NPTS*CH/2];
__device__ __half2 g_hiB[NPTS*CH/2];
__device__ uint32_t g_wswz[5*KN*2048];      // W_hi fp16, mma-fragment packed (8KB/tap)
__device__ float g_sum[5*CH], g_sumsq[5*CH];
__device__ float g_segsum[NB*CAQ], g_segmax[NB*CAQ], g_att[NB*CAQ], g_wsig[NXX];
__device__ int g_cnt0;

// ---------------- helpers ----------------------------------------------------
__device__ __forceinline__ uint32_t smem_u32(const void* p){
  uint32_t a;
  asm("{ .reg .u64 t; cvta.to.shared.u64 t, %1; cvt.u32.u64 %0, t; }" : "=r"(a) : "l"(p));
  return a;
}
__device__ __forceinline__ void ldsm_x4(uint32_t addr, uint32_t* r){
  asm volatile("ldmatrix.sync.aligned.m8n8.x4.shared.b16 {%0,%1,%2,%3}, [%4];"
    : "=r"(r[0]),"=r"(r[1]),"=r"(r[2]),"=r"(r[3]) : "r"(addr));
}
__device__ __forceinline__ void hmma(float* c, const uint32_t* a, uint32_t b0, uint32_t b1){
  asm volatile(
    "mma.sync.aligned.m16n8k16.row.col.f32.f16.f16.f32 "
    "{%0,%1,%2,%3}, {%4,%5,%6,%7}, {%8,%9}, {%0,%1,%2,%3};"
    : "+f"(c[0]), "+f"(c[1]), "+f"(c[2]), "+f"(c[3])
    : "r"(a[0]), "r"(a[1]), "r"(a[2]), "r"(a[3]), "r"(b0), "r"(b1));
}
__device__ __forceinline__ void cp16z(uint32_t sdst, const void* gsrc, int srcsz){
  asm volatile("cp.async.cg.shared.global [%0], [%1], 16, %2;" :: "r"(sdst), "l"(gsrc), "r"(srcsz));
}
#define CP_COMMIT() asm volatile("cp.async.commit_group;" ::: "memory")
#define CP_WAIT2()  asm volatile("cp.async.wait_group 2;" ::: "memory")
#define PAIR_BAR(id) asm volatile("bar.sync %0, 64;" :: "r"(id) : "memory")

__device__ __forceinline__ void atomicMaxFloat(float* addr, float val){
  int* ai = (int*)addr;
  int old = *ai;
  while (true){
    float fo = __int_as_float(old);
    if (fo >= val) break;
    int assumed = old;
    old = atomicCAS(ai, assumed, __float_as_int(val));
    if (old == assumed) break;
  }
}

// ---------------- merged prep: cvt (5000 blk) + wprep (135 blk) + clear (2) --
__global__ void prep_kernel(const float4* __restrict__ x, __half2* __restrict__ ho,
                            const float* __restrict__ W1, const float* __restrict__ W2,
                            const float* __restrict__ Wk){
  int b = blockIdx.x;
  int t = threadIdx.x;
  if (b < 5000){
    int i4 = b*256 + t;
    float4 v = x[i4];
    ho[2*i4]   = __halves2half2(__float2half(v.x), __float2half(v.y));
    ho[2*i4+1] = __halves2half2(__float2half(v.z), __float2half(v.w));
  } else if (b < 5000 + 5*KN){
    __shared__ float wt[4096];
    int tk = b - 5000;
    int l = tk/KN, k = tk - l*KN;
    const float* Ws = ((l==0)? W1 : (l==1)? W2 : (Wk + (size_t)(l-2)*KN*CH*CH)) + (size_t)k*CH*CH;
    for (int i = t; i < 4096; i += 256) wt[i] = Ws[i];
    __syncthreads();
    for (int slot = t; slot < 2048; slot += 256){
      int r    = slot & 3;
      int L    = (slot >> 2) & 31;
      int rest = slot >> 7;
      int quad = rest & 1;
      int q    = (rest >> 1) & 3;
      int wn   = rest >> 3;
      int n  = wn*32 + quad*16 + (r>>1)*8 + (L>>2);
      int kk = q*16 + (L&3)*2 + (r&1)*8;
      __half b0 = __float2half(wt[kk*CH + n]);
      __half b1 = __float2half(wt[(kk+1)*CH + n]);
      g_wswz[tk*2048 + slot] =
          (uint32_t)__half_as_ushort(b0) | ((uint32_t)__half_as_ushort(b1) << 16);
    }
  } else {
    int i = (b - 5000 - 5*KN)*256 + t;
    if (i < 5*CH){ g_sum[i]=0.f; g_sumsq[i]=0.f; }
    if (i < NB*CAQ){ g_segsum[i]=0.f; g_segmax[i]=-FLT_MAX; }
    if (i == 5*CH) g_cnt0 = 0;
  }
}

// ---------------- HMMA gathered conv (unchanged body) -----------------------
#define NBR_OFF 65536
#define SM_DYN (65536 + 13824 + 1024)

__device__ __forceinline__ void ldgB(const uint4* __restrict__ bw,
                                     int k, int q, int wn, int L, uint32_t* B){
  const uint4* p = bw + (size_t)k*512 + (size_t)((wn*4 + q)*2)*32 + L;
  uint4 v0 = __ldg(p);
  uint4 v1 = __ldg(p + 32);
  B[0]=v0.x; B[1]=v0.y; B[2]=v0.z; B[3]=v0.w;
  B[4]=v1.x; B[5]=v1.y; B[6]=v1.z; B[7]=v1.w;
}

__device__ __forceinline__ void fillA(
    int k, int buf, int t, uint32_t sb, const int* __restrict__ snbr,
    const __half* __restrict__ hi)
{
  int r = (t>>6)*32 + ((t&63)>>1);
  int half = t & 1;
  int idx = snbr[r*KN + k];
  int sz = idx>=0 ? 16 : 0;
  int sidx = idx>=0 ? idx : 0;
  const char* asrc = (const char*)(hi + (size_t)sidx*CH);
  uint32_t rbase = sb + (uint32_t)buf*16384 + (uint32_t)r*128;
  int xr = r & 7;
#pragma unroll
  for (int j=0;j<4;j++){
    int c = half*4 + j;
    int sw = c ^ xr;
    cp16z(rbase + sw*16, asrc + c*16, sz);
  }
}

__global__ void __launch_bounds__(256,2) conv_mma(
    const __half* __restrict__ hi,
    const int* __restrict__ nbr, const uint32_t* __restrict__ bswz,
    __half* __restrict__ dst, int layer)
{
  extern __shared__ char smraw[];
  char* sm = (char*)(((uintptr_t)smraw + 1023) & ~(uintptr_t)1023);
  const uint32_t sb = smem_u32(sm);
  int* snbr = (int*)(sm + NBR_OFF);
  __shared__ float sred[128];
  const uint4* bw = (const uint4*)bswz;

  const int t   = threadIdx.x;
  const int L   = t & 31;
  const int wid = t >> 5;
  const int wm  = wid >> 1;
  const int wn  = wid & 1;
  const int barid = 1 + wm;

  const int arow_l  = ((L>>3)&1)*8 + (L&7);
  const int a_clane = (L>>4);
  const int arow    = wm*32 + arow_l;
  const int axor    = arow & 7;

  for (int tile = blockIdx.x; tile < NTILES; tile += GRIDC){
    const int row0 = tile * 128;

    if (t < 128) sred[t] = 0.f;

    {
      const int* src = nbr + (size_t)row0*KN;
#pragma unroll
      for (int i = 0; i < 14; i++){
        int o = t + i*256;
        if (o < 128*KN) snbr[o] = src[o];
      }
    }
    __syncthreads();

    float acc[2][4][4];
#pragma unroll
    for (int s=0;s<2;s++)
#pragma unroll
      for (int nb=0;nb<4;nb++)
#pragma unroll
        for (int i=0;i<4;i++) acc[s][nb][i]=0.f;

    fillA(0, 0, t, sb, snbr, hi); CP_COMMIT();
    fillA(1, 1, t, sb, snbr, hi); CP_COMMIT();
    fillA(2, 2, t, sb, snbr, hi); CP_COMMIT();

    uint32_t Bb0[8], Bb1[8];
    ldgB(bw, 0, 0, wn, L, Bb0);

    for (int k = 0; k < KN; k++){
      CP_WAIT2();
      PAIR_BAR(barid);

      if (k+3 < KN) fillA(k+3, (k+3)&3, t, sb, snbr, hi);
      CP_COMMIT();

      const uint32_t Arow = sb + (uint32_t)(k&3)*16384 + (uint32_t)arow*128;

#pragma unroll
      for (int q=0; q<4; q++){
        uint32_t* Bcur = (q&1) ? Bb1 : Bb0;
        uint32_t* Bnxt = (q&1) ? Bb0 : Bb1;
        if (q < 3) ldgB(bw, k, q+1, wn, L, Bnxt);
        else       ldgB(bw, (k+1<KN)?(k+1):k, 0, wn, L, Bnxt);

        uint32_t Ah0[4], Ah1[4];
        uint32_t ah = Arow + (uint32_t)(((q*2 + a_clane) ^ axor)*16);
        ldsm_x4(ah, Ah0);
        ldsm_x4(ah + 16*128, Ah1);

        hmma(acc[0][0], Ah0, Bcur[0], Bcur[1]);
        hmma(acc[0][1], Ah0, Bcur[2], Bcur[3]);
        hmma(acc[0][2], Ah0, Bcur[4], Bcur[5]);
        hmma(acc[0][3], Ah0, Bcur[6], Bcur[7]);
        hmma(acc[1][0], Ah1, Bcur[0], Bcur[1]);
        hmma(acc[1][1], Ah1, Bcur[2], Bcur[3]);
        hmma(acc[1][2], Ah1, Bcur[4], Bcur[5]);
        hmma(acc[1][3], Ah1, Bcur[6], Bcur[7]);
      }
    }

    // ---- epilogue: fp16 stores + fused per-channel stats (fp32 accs)
#pragma unroll
    for (int s=0;s<2;s++){
      int r = row0 + wm*32 + s*16 + (L>>2);
#pragma unroll
      for (int nb=0;nb<4;nb++){
        int col = wn*32 + nb*8 + (L&3)*2;
        float* c = acc[s][nb];
        *(__half2*)&dst[(size_t)r*CH + col]     = __floats2half2_rn(c[0], c[1]);
        *(__half2*)&dst[(size_t)(r+8)*CH + col] = __floats2half2_rn(c[2], c[3]);
      }
    }
#pragma unroll
    for (int nb=0;nb<4;nb++){
      float sc0=0.f, sc1=0.f, qc0=0.f, qc1=0.f;
#pragma unroll
      for (int s=0;s<2;s++){
        float* c = acc[s][nb];
        sc0 += c[0]+c[2]; qc0 += c[0]*c[0]+c[2]*c[2];
        sc1 += c[1]+c[3]; qc1 += c[1]*c[1]+c[3]*c[3];
      }
#pragma unroll
      for (int m=4;m<32;m<<=1){
        sc0 += __shfl_xor_sync(0xFFFFFFFFu, sc0, m);
        sc1 += __shfl_xor_sync(0xFFFFFFFFu, sc1, m);
        qc0 += __shfl_xor_sync(0xFFFFFFFFu, qc0, m);
        qc1 += __shfl_xor_sync(0xFFFFFFFFu, qc1, m);
      }
      if (L < 4){
        int col = wn*32 + nb*8 + L*2;
        atomicAdd(&sred[col],    sc0); atomicAdd(&sred[col+1],    sc1);
        atomicAdd(&sred[64+col], qc0); atomicAdd(&sred[64+col+1], qc1);
      }
    }
    __syncthreads();
    if (t < 64){
      atomicAdd(&g_sum[layer*CH + t],   sred[t]);
      atomicAdd(&g_sumsq[layer*CH + t], sred[64+t]);
    }
    __syncthreads();
  }
}

// ---------------- BN apply (fp16 in) -> single fp16 output ------------------
__global__ void bn2_kernel(const __half* __restrict__ x, const float* __restrict__ gg,
                           const float* __restrict__ bb, int relu, int layer,
                           __half2* __restrict__ outp){
  __shared__ float sc[64], bi[64];
  int t = threadIdx.x;
  if (t < 64){
    float m = g_sum[layer*CH + t]*(1.f/NPTS);
    float v = g_sumsq[layer*CH + t]*(1.f/NPTS) - m*m;
    float s = rsqrtf(v + 1e-5f) * gg[t];
    sc[t] = s; bi[t] = bb[t] - m*s;
  }
  __syncthreads();
  int i4 = blockIdx.x*256 + t;
  uint2 hv = ((const uint2*)x)[i4];
  float2 f01 = __half22float2(*(__half2*)&hv.x);
  float2 f23 = __half22float2(*(__half2*)&hv.y);
  int c = (i4 & 15)*4;
  float v0 = f01.x*sc[c]  +bi[c];
  float v1 = f01.y*sc[c+1]+bi[c+1];
  float v2 = f23.x*sc[c+2]+bi[c+2];
  float v3 = f23.y*sc[c+3]+bi[c+3];
  if (relu){ v0=fmaxf(v0,0.f); v1=fmaxf(v1,0.f); v2=fmaxf(v2,0.f); v3=fmaxf(v3,0.f); }
  outp[2*i4]   = __floats2half2_rn(v0, v1);
  outp[2*i4+1] = __floats2half2_rn(v2, v3);
}

// ---------------- layer-4 bn params helper ----------------------------------
__device__ __forceinline__ void bn4_params(int t, const float* gk2, const float* bk2,
                                           float* sc, float* bi){
  if (t < 64){
    float m = g_sum[4*CH + t]*(1.f/NPTS);
    float v = g_sumsq[4*CH + t]*(1.f/NPTS) - m*m;
    float s = rsqrtf(v + 1e-5f) * gk2[t];
    sc[t] = s; bi[t] = bk2[t] - m*s;
  }
}

// ---------------- segment sum/max + batch count (kx2 inline from conv) ------
__global__ void seg_kernel(const int* __restrict__ bidx,
                           const float* __restrict__ gk2, const float* __restrict__ bk2){
  __shared__ float sc[64], bi[64];
  int j = threadIdx.x;
  bn4_params(j, gk2, bk2, sc, bi);
  __syncthreads();
  int c = j & 63;
  int n0 = blockIdx.x*200, n1 = n0+200;
  float s0=0.f, s1=0.f, m0=-FLT_MAX, m1=-FLT_MAX;
  int cnt0 = 0;
  if (j < 128){
    const __half* kxp = (j<64)? g_kx0 : g_kx1;
    for (int n=n0;n<n1;n++){
      int b = bidx[n];
      float v = __half2float(kxp[n*CH + c]);
      if (b==0){ s0+=v; m0=fmaxf(m0,v); cnt0++; } else { s1+=v; m1=fmaxf(m1,v); }
    }
  } else {
    float scv = sc[c], biv = bi[c];
    for (int n=n0;n<n1;n++){
      int b = bidx[n];
      float v = fmaxf(__half2float(g_conv[n*CH + c])*scv + biv, 0.f);
      if (b==0){ s0+=v; m0=fmaxf(m0,v); } else { s1+=v; m1=fmaxf(m1,v); }
    }
  }
  atomicAdd(&g_segsum[j], s0);
  atomicAdd(&g_segsum[CAQ+j], s1);
  atomicMaxFloat(&g_segmax[j], m0);
  atomicMaxFloat(&g_segmax[CAQ+j], m1);
  if (j == 0) atomicAdd(&g_cnt0, cnt0);
}

// ---------------- tiny FC + sigmoid attention ------------------------------
__global__ void fc_kernel(const float* __restrict__ w1, const float* __restrict__ b1,
                          const float* __restrict__ w2, const float* __restrict__ b2,
                          const float* __restrict__ ksw)
{
  __shared__ float ha[NB][HID], hm[NB][HID];
  int t = threadIdx.x;
  int cnt0 = g_cnt0;
  if (t<48){
    int which = t/24;
    int b  = (t/12)%2;
    int tt = t%12;
    float s = b1[tt];
    float inv = 1.f/(float)(b==0 ? cnt0 : NPTS-cnt0);
    for (int j=0;j<CAQ;j++){
      float z = which ? g_segmax[b*CAQ+j] : g_segsum[b*CAQ+j]*inv;
      s += z * w1[j*HID+tt];
    }
    s = fmaxf(s,0.f);
    if (which) hm[b][tt]=s; else ha[b][tt]=s;
  }
  __syncthreads();
  for (int o=t; o<NB*CAQ; o+=256){
    int b=o/CAQ, j=o%CAQ;
    float sa=b2[j], sm=b2[j];
    for (int tt=0;tt<HID;tt++){ sa += ha[b][tt]*w2[tt*CAQ+j]; sm += hm[b][tt]*w2[tt*CAQ+j]; }
    float s = sa+sm;
    g_att[o] = 1.f/(1.f+expf(-s));
  }
  if (t<NXX) g_wsig[t] = 1.f/(1.f+expf(-ksw[t]));
}

// ---------------- fusion epilogue (kx2 inline from conv) --------------------
__global__ void final_kernel(const float* __restrict__ feats,
                             const int* __restrict__ bidx,
                             const float* __restrict__ gk2, const float* __restrict__ bk2,
                             float* __restrict__ out){
  __shared__ float sc[64], bi[64];
  int t = threadIdx.x;
  bn4_params(t, gk2, bk2, sc, bi);
  __syncthreads();
  int i = blockIdx.x*256 + t;
  int n = i >> 6, c = i & 63;
  int b = bidx[n];
  float acc = feats[i];
#pragma unroll
  for (int ii=0; ii<NXX; ii++){
    int j = 3*c + ii;
    int sel = j >> 6, col = j & 63;
    float xj;
    if (sel == 0)      xj = __half2float(g_kx0[n*CH + col]);
    else if (sel == 1) xj = __half2float(g_kx1[n*CH + col]);
    else               xj = fmaxf(__half2float(g_conv[n*CH + col])*sc[col] + bi[col], 0.f);
    float kxi;
    if (ii == 0)      kxi = __half2float(g_kx0[i]);
    else if (ii == 1) kxi = __half2float(g_kx1[i]);
    else              kxi = fmaxf(__half2float(g_conv[i])*sc[c] + bi[c], 0.f);
    acc += g_wsig[ii] * (kxi + xj * g_att[b*CAQ + j]);
  }
  out[i] = fmaxf(acc, 0.f);
}

// ---------------- launch ----------------------------------------------------
extern "C" void kernel_launch(void* const* d_in, const int* in_sizes, int n_in,
                              void* d_out, int out_size){
  (void)in_sizes; (void)n_in; (void)out_size;
  const float* feats=(const float*)d_in[0];
  const int*   bidx =(const int*)d_in[1];
  const int*   nbr  =(const int*)d_in[2];
  const float* W1 =(const float*)d_in[3];
  const float* g1 =(const float*)d_in[4];
  const float* b1 =(const float*)d_in[5];
  const float* W2 =(const float*)d_in[6];
  const float* g2 =(const float*)d_in[7];
  const float* b2 =(const float*)d_in[8];
  const float* Wk =(const float*)d_in[9];
  const float* gk =(const float*)d_in[10];
  const float* bk =(const float*)d_in[11];
  const float* fc1w=(const float*)d_in[12];
  const float* fc1b=(const float*)d_in[13];
  const float* fc2w=(const float*)d_in[14];
  const float* fc2b=(const float*)d_in[15];
  const float* ksw =(const float*)d_in[16];
  float* out=(float*)d_out;

  __half *pConv,*pk0,*pk1;
  __half2 *pHiA,*pHiB;
  uint32_t* pW;
  cudaGetSymbolAddress((void**)&pConv, g_conv);
  cudaGetSymbolAddress((void**)&pk0, g_kx0);
  cudaGetSymbolAddress((void**)&pk1, g_kx1);
  cudaGetSymbolAddress((void**)&pHiA, g_hiA);
  cudaGetSymbolAddress((void**)&pHiB, g_hiB);
  cudaGetSymbolAddress((void**)&pW,  g_wswz);

  cudaFuncSetAttribute(conv_mma, cudaFuncAttributeMaxDynamicSharedMemorySize, SM_DYN);

  prep_kernel<<<5000 + 5*KN + 2, 256>>>((const float4*)feats, pHiA, W1, W2, Wk);

  struct Step {
    const __half *hi; const uint32_t* bw;
    const float *g, *b; int relu;
    __half2* outp;
  };
  Step steps[5] = {
    {(const __half*)pHiA, pW + 0*KN*2048, g1,      b1,      1, pHiB},
    {(const __half*)pHiB, pW + 1*KN*2048, g2,      b2,      0, pHiA},
    {(const __half*)pHiA, pW + 2*KN*2048, gk,      bk,      1, (__half2*)pk0},
    {(const __half*)pk0,  pW + 3*KN*2048, gk+CH,   bk+CH,   1, (__half2*)pk1},
    {(const __half*)pk1,  pW + 4*KN*2048, gk+2*CH, bk+2*CH, 1, nullptr},
  };
  for (int s=0;s<5;s++){
    conv_mma<<<GRIDC, 256, SM_DYN>>>(steps[s].hi, nbr, steps[s].bw, pConv, s);
    if (s < 4)
      bn2_kernel<<<NPTS*CH/4/256, 256>>>(pConv, steps[s].g, steps[s].b, steps[s].relu, s,
                                         steps[s].outp);
  }
  seg_kernel<<<400, CAQ>>>(bidx, gk+2*CH, bk+2*CH);
  fc_kernel<<<1,256>>>(fc1w, fc1b, fc2w, fc2b, ksw);
  final_kernel<<<(NPTS*CH)/256, 256>>>(feats, bidx, gk+2*CH, bk+2*CH, out);
}